// round 12
// baseline (speedup 1.0000x reference)
#include <cuda_runtime.h>
#include <cuda_bf16.h>
#include <math.h>
#include <stdint.h>

#define NN 50000
#define DD 128
#define EE 500000
#define NT32 (EE / 32)   // 15625 pair-tiles, exact

// ---------------- device scratch ----------------
static __device__ __nv_bfloat16 g_A1a[NN*DD];   // lrelu(x_a@Wp.T+bp)@W1p.T + b1
static __device__ __nv_bfloat16 g_C1a[NN*DD];   // lrelu(x_a@Wc.T+bc)@W1c.T
static __device__ __nv_bfloat16 g_A1b[NN*DD];
static __device__ __nv_bfloat16 g_C1b[NN*DD];
static __device__ __nv_bfloat16 g_xa16[NN*DD];  // bf16 copies of x (gather path)
static __device__ __nv_bfloat16 g_xb16[NN*DD];
static __device__ float g_msg_a[NN*DD];
static __device__ float g_msg_b[NN*DD];

__device__ __forceinline__ uint32_t smem_u32(const void* p) {
    uint32_t a;
    asm("{ .reg .u64 t; cvta.to.shared.u64 t, %1; cvt.u32.u64 %0, t; }" : "=r"(a) : "l"(p));
    return a;
}
__device__ __forceinline__ void ldsm_x4(uint32_t* r, uint32_t addr) {
    asm volatile("ldmatrix.sync.aligned.m8n8.x4.shared.b16 {%0,%1,%2,%3}, [%4];"
                 : "=r"(r[0]), "=r"(r[1]), "=r"(r[2]), "=r"(r[3]) : "r"(addr));
}
__device__ __forceinline__ void ldsm_x2(uint32_t* r, uint32_t addr) {
    asm volatile("ldmatrix.sync.aligned.m8n8.x2.shared.b16 {%0,%1}, [%2];"
                 : "=r"(r[0]), "=r"(r[1]) : "r"(addr));
}
__device__ __forceinline__ void mma_bf16(float* c, const uint32_t* a, const uint32_t* b) {
    asm volatile("mma.sync.aligned.m16n8k16.row.col.f32.bf16.bf16.f32 "
                 "{%0,%1,%2,%3}, {%4,%5,%6,%7}, {%8,%9}, {%0,%1,%2,%3};"
                 : "+f"(c[0]), "+f"(c[1]), "+f"(c[2]), "+f"(c[3])
                 : "r"(a[0]), "r"(a[1]), "r"(a[2]), "r"(a[3]), "r"(b[0]), "r"(b[1]));
}
__device__ __forceinline__ void red_add_v4(float* p, float a, float b, float c, float d) {
    asm volatile("red.global.add.v4.f32 [%0], {%1, %2, %3, %4};"
                 :: "l"(p), "f"(a), "f"(b), "f"(c), "f"(d) : "memory");
}
__device__ __forceinline__ __nv_bfloat162 u2bf2(uint32_t u) {
    return *reinterpret_cast<__nv_bfloat162*>(&u);
}
__device__ __forceinline__ uint32_t bf2u(__nv_bfloat162 h) {
    return *reinterpret_cast<uint32_t*>(&h);
}

// 16-row x 128-col x K=128 warp MMA over stride-272 bf16 smem tiles; accumulates.
__device__ __forceinline__ void mma_rows16(uint32_t a_addr0, uint32_t b_base, float acc[16][4]) {
    #pragma unroll
    for (int k = 0; k < 8; k++) {
        uint32_t afrag[4];
        ldsm_x4(afrag, a_addr0 + k * 32);
        uint32_t bb = b_base + k * 32;
        #pragma unroll
        for (int nt = 0; nt < 16; nt++) {
            uint32_t bfrag[2];
            ldsm_x2(bfrag, bb + nt * 2176);
            mma_bf16(acc[nt], afrag, bfrag);
        }
    }
}

// ---------------- zero msg + make bf16 x copies ----------------
__global__ void zero_cvt_kernel(const float* __restrict__ xa, const float* __restrict__ xb) {
    int i = blockIdx.x * blockDim.x + threadIdx.x;
    if (i < NN * DD / 4) {
        float4 z = make_float4(0.f, 0.f, 0.f, 0.f);
        reinterpret_cast<float4*>(g_msg_a)[i] = z;
        reinterpret_cast<float4*>(g_msg_b)[i] = z;
        float4 a = reinterpret_cast<const float4*>(xa)[i];
        float4 b = reinterpret_cast<const float4*>(xb)[i];
        uint2 pa, pb;
        pa.x = bf2u(__floats2bfloat162_rn(a.x, a.y));
        pa.y = bf2u(__floats2bfloat162_rn(a.z, a.w));
        pb.x = bf2u(__floats2bfloat162_rn(b.x, b.y));
        pb.y = bf2u(__floats2bfloat162_rn(b.z, b.w));
        reinterpret_cast<uint2*>(g_xa16)[i] = pa;
        reinterpret_cast<uint2*>(g_xb16)[i] = pb;
    }
}

// ---------------- node precompute: merged chains per side ----------------
#define NP_WT   0         // bf16 [128][272] -> 34816
#define NP_UT   34816     // bf16 [128][272] -> 69632
#define NP_XS   69632     // bf16 [256][272] -> 139264
#define NP_TS   139264    // bf16 [256][272] -> 208896
#define NP_BENC 208896    // 2 x 128 floats (bp, bc)
#define NP_B1   209920    // 128 floats
#define NP_TOTAL 210432

__global__ __launch_bounds__(512, 1) void node_pre_kernel(
    const float* __restrict__ x_a, const float* __restrict__ x_b,
    const float* __restrict__ Wp, const float* __restrict__ bp,
    const float* __restrict__ Wc, const float* __restrict__ bc,
    const float* __restrict__ W1, const float* __restrict__ b1)
{
    extern __shared__ char smc[];
    uint32_t smb = smem_u32(smc);
    float* benc = (float*)(smc + NP_BENC);
    float* b1sm = (float*)(smc + NP_B1);

    int sidex = blockIdx.y;
    const float* X = sidex ? x_b : x_a;
    __nv_bfloat16* OutA = sidex ? g_A1b : g_A1a;
    __nv_bfloat16* OutC = sidex ? g_C1b : g_C1a;

    int tid = threadIdx.x, lane = tid & 31, w = tid >> 5;
    int nbase = blockIdx.x * 256;

    for (int idx = tid; idx < 256 * 32; idx += 512) {
        int row = idx >> 5, cp = idx & 31;
        int n = nbase + row;
        float4 f = make_float4(0.f, 0.f, 0.f, 0.f);
        if (n < NN) f = *reinterpret_cast<const float4*>(X + (size_t)n * 128 + cp * 4);
        uint2 pk;
        pk.x = bf2u(__floats2bfloat162_rn(f.x, f.y));
        pk.y = bf2u(__floats2bfloat162_rn(f.z, f.w));
        *reinterpret_cast<uint2*>(smc + NP_XS + row * 272 + cp * 8) = pk;
    }
    if (tid < 128) {
        benc[tid]       = bp[tid];
        benc[128 + tid] = bc[tid];
        b1sm[tid]       = b1[tid];
    }

    uint32_t a_lane_off = (uint32_t)(lane & 15) * 272 + (((uint32_t)lane >> 4) << 4);
    uint32_t b_lane_off = (uint32_t)(lane & 7) * 272 + ((((uint32_t)lane >> 3) & 1) << 4);
    int r0 = 16 * w + (lane >> 2), r1 = r0 + 8;
    int cq = (lane & 3) * 2;
    int n0 = nbase + r0, n1 = nbase + r1;

    for (int cc = 0; cc < 2; cc++) {
        const float* W = cc ? Wc : Wp;
        int off = cc ? 128 : 0;
        __nv_bfloat16* Out = cc ? OutC : OutA;

        for (int idx = tid; idx < 128 * 64; idx += 512) {
            int i = idx >> 6, cp = idx & 63;
            float2 fw = *reinterpret_cast<const float2*>(W + i * 128 + cp * 2);
            float2 fu = *reinterpret_cast<const float2*>(W1 + i * 384 + off + cp * 2);
            *(uint32_t*)(smc + NP_WT + i * 272 + cp * 4) = bf2u(__floats2bfloat162_rn(fw.x, fw.y));
            *(uint32_t*)(smc + NP_UT + i * 272 + cp * 4) = bf2u(__floats2bfloat162_rn(fu.x, fu.y));
        }
        __syncthreads();

        float acc[16][4];
        #pragma unroll
        for (int nt = 0; nt < 16; nt++)
            #pragma unroll
            for (int q = 0; q < 4; q++) acc[nt][q] = 0.f;
        mma_rows16(smb + NP_XS + (uint32_t)(16 * w) * 272 + a_lane_off, smb + NP_WT + b_lane_off, acc);

        #pragma unroll
        for (int nt = 0; nt < 16; nt++) {
            int c = nt * 8 + cq;
            float2 bb = *reinterpret_cast<const float2*>(benc + cc * 128 + c);
            float v0 = acc[nt][0] + bb.x, v1 = acc[nt][1] + bb.y;
            float v2 = acc[nt][2] + bb.x, v3 = acc[nt][3] + bb.y;
            v0 = v0 > 0.f ? v0 : 0.01f * v0;
            v1 = v1 > 0.f ? v1 : 0.01f * v1;
            v2 = v2 > 0.f ? v2 : 0.01f * v2;
            v3 = v3 > 0.f ? v3 : 0.01f * v3;
            *(uint32_t*)(smc + NP_TS + r0 * 272 + c * 2) = bf2u(__floats2bfloat162_rn(v0, v1));
            *(uint32_t*)(smc + NP_TS + r1 * 272 + c * 2) = bf2u(__floats2bfloat162_rn(v2, v3));
        }
        __syncwarp();

        #pragma unroll
        for (int nt = 0; nt < 16; nt++)
            #pragma unroll
            for (int q = 0; q < 4; q++) acc[nt][q] = 0.f;
        mma_rows16(smb + NP_TS + (uint32_t)(16 * w) * 272 + a_lane_off, smb + NP_UT + b_lane_off, acc);

        #pragma unroll
        for (int nt = 0; nt < 16; nt++) {
            int c = nt * 8 + cq;
            float bx = (cc == 0) ? b1sm[c] : 0.f;
            float by = (cc == 0) ? b1sm[c + 1] : 0.f;
            uint32_t h0 = bf2u(__floats2bfloat162_rn(acc[nt][0] + bx, acc[nt][1] + by));
            uint32_t h1 = bf2u(__floats2bfloat162_rn(acc[nt][2] + bx, acc[nt][3] + by));
            if (n0 < NN) *(uint32_t*)(Out + (size_t)n0 * 128 + c) = h0;
            if (n1 < NN) *(uint32_t*)(Out + (size_t)n1 * 128 + c) = h1;
        }
        __syncthreads();
    }
}

// ---------------- edge kernel: 32-edge pair-tiles, 2 CTAs/SM ----------------
#define EP_W2   0          // 128 floats -> 512
#define EP_W1D  512        // bf16 [128][272] -> 35328
#define EP_DIFF 35328      // 4 pairs x 32x272 -> 70144
#define EP_PRES 70144      // 4 pairs x 32x272 -> 104960
#define EP_ZB   104960     // 4 pairs x 64 floats -> 105984
#define EP_TOTAL 105984

__global__ __launch_bounds__(256, 2) void edge_mma_kernel(
    const float* __restrict__ x_a, const float* __restrict__ x_b,
    const int* __restrict__ ei,
    const float* __restrict__ W1,
    const float* __restrict__ W2, const float* __restrict__ b2,
    int side)
{
    extern __shared__ char smc[];
    uint32_t smb = smem_u32(smc);
    float* w2s  = (float*)(smc + EP_W2);
    float* zbuf = (float*)(smc + EP_ZB);

    const float* src = side ? x_b : x_a;                     // fp32, scatter only
    const __nv_bfloat16* s16 = side ? g_xb16 : g_xa16;
    const __nv_bfloat16* d16 = side ? g_xa16 : g_xb16;
    const __nv_bfloat16* A1 = side ? g_A1b : g_A1a;
    const __nv_bfloat16* C1 = side ? g_C1a : g_C1b;
    float* msg              = side ? g_msg_a : g_msg_b;

    int tid = threadIdx.x, lane = tid & 31, w = tid >> 5;
    int pair = w >> 1, hf = w & 1;

    for (int idx = tid; idx < 128 * 64; idx += 256) {
        int i = idx >> 6, cp = idx & 63;
        float2 f = *reinterpret_cast<const float2*>(W1 + i * 384 + 256 + cp * 2);
        *(uint32_t*)(smc + EP_W1D + i * 272 + cp * 4) = bf2u(__floats2bfloat162_rn(f.x, f.y));
    }
    if (tid < 128) w2s[tid] = W2[tid];
    float b2s = __ldg(b2);
    __syncthreads();

    uint32_t tile_off = (uint32_t)pair * 8704;   // 32 rows x 272B
    uint32_t a_base = smb + EP_DIFF + tile_off + (uint32_t)(lane & 15) * 272 + (((uint32_t)lane >> 4) << 4);
    uint32_t b_base = smb + EP_W1D + (uint32_t)(lane & 7) * 272 + ((((uint32_t)lane >> 3) & 1) << 4)
                    + (uint32_t)hf * (8 * 2176);
    int r0 = lane >> 2;               // base row within pair tile (0..7)
    int cq = (lane & 3) * 2;
    int chf = hf * 64;
    int zidx = pair * 64;

    const int pstride = gridDim.x * 4;
    int pt = blockIdx.x * 4 + pair;
    if (pt >= NT32) return;

    // 32 src + 32 dst indices: one coalesced load each
    int vs = __ldg(ei + pt * 32 + lane);
    int vt = __ldg(ei + EE + pt * 32 + lane);

    while (true) {
        // ---- gather: this warp fills rows 16*hf .. +15 of the 32-row pair tile ----
        #pragma unroll
        for (int i = 0; i < 16; i++) {
            int ii = 16 * hf + i;
            int s = __shfl_sync(0xffffffffu, vs, ii);
            int t = __shfl_sync(0xffffffffu, vt, ii);
            uint2 pu  = *reinterpret_cast<const uint2*>(s16 + (size_t)s * 128 + 4 * lane);
            uint2 cu  = *reinterpret_cast<const uint2*>(d16 + (size_t)t * 128 + 4 * lane);
            uint2 a1u = *reinterpret_cast<const uint2*>(A1  + (size_t)s * 128 + 4 * lane);
            uint2 c1u = *reinterpret_cast<const uint2*>(C1  + (size_t)t * 128 + 4 * lane);
            uint2 dpk, ppk;
            dpk.x = bf2u(__habs2(__hsub2(u2bf2(pu.x), u2bf2(cu.x))));
            dpk.y = bf2u(__habs2(__hsub2(u2bf2(pu.y), u2bf2(cu.y))));
            ppk.x = bf2u(__hadd2(u2bf2(a1u.x), u2bf2(c1u.x)));
            ppk.y = bf2u(__hadd2(u2bf2(a1u.y), u2bf2(c1u.y)));
            *reinterpret_cast<uint2*>(smc + EP_DIFF + tile_off + ii * 272 + lane * 8) = dpk;
            *reinterpret_cast<uint2*>(smc + EP_PRES + tile_off + ii * 272 + lane * 8) = ppk;
        }
        asm volatile("bar.sync %0, 64;" :: "r"(pair + 1) : "memory");

        // ---- prefetch next pair-tile's indices ----
        int ptn = pt + pstride;
        int vs_n = 0, vt_n = 0;
        if (ptn < NT32) {
            vs_n = __ldg(ei + ptn * 32 + lane);
            vt_n = __ldg(ei + EE + ptn * 32 + lane);
        }

        // ---- mma: 2 m-tiles (32 edges) x this warp's 8 n-tiles ----
        float acc0[8][4], acc1[8][4];
        #pragma unroll
        for (int nt = 0; nt < 8; nt++)
            #pragma unroll
            for (int q = 0; q < 4; q++) { acc0[nt][q] = 0.f; acc1[nt][q] = 0.f; }
        #pragma unroll
        for (int k = 0; k < 8; k++) {
            uint32_t a0[4], a1f[4];
            ldsm_x4(a0,  a_base + k * 32);
            ldsm_x4(a1f, a_base + 4352 + k * 32);
            uint32_t bb = b_base + k * 32;
            #pragma unroll
            for (int nt = 0; nt < 8; nt++) {
                uint32_t bfrag[2];
                ldsm_x2(bfrag, bb + nt * 2176);
                mma_bf16(acc0[nt], a0,  bfrag);
                mma_bf16(acc1[nt], a1f, bfrag);
            }
        }

        // ---- epilogue: partial z over this warp's 64 cols, 4 row-slots ----
        float z0 = 0.f, z1 = 0.f, z2 = 0.f, z3 = 0.f;
        #pragma unroll
        for (int nt = 0; nt < 8; nt++) {
            int c = chf + nt * 8 + cq;
            float2 w2v = *reinterpret_cast<const float2*>(w2s + c);
            float2 p0 = __bfloat1622float2(*reinterpret_cast<const __nv_bfloat162*>(smc + EP_PRES + tile_off + (r0     ) * 272 + c * 2));
            float2 p1 = __bfloat1622float2(*reinterpret_cast<const __nv_bfloat162*>(smc + EP_PRES + tile_off + (r0 +  8) * 272 + c * 2));
            float2 p2 = __bfloat1622float2(*reinterpret_cast<const __nv_bfloat162*>(smc + EP_PRES + tile_off + (r0 + 16) * 272 + c * 2));
            float2 p3 = __bfloat1622float2(*reinterpret_cast<const __nv_bfloat162*>(smc + EP_PRES + tile_off + (r0 + 24) * 272 + c * 2));
            z0 += fmaxf(p0.x + acc0[nt][0], 0.f) * w2v.x + fmaxf(p0.y + acc0[nt][1], 0.f) * w2v.y;
            z1 += fmaxf(p1.x + acc0[nt][2], 0.f) * w2v.x + fmaxf(p1.y + acc0[nt][3], 0.f) * w2v.y;
            z2 += fmaxf(p2.x + acc1[nt][0], 0.f) * w2v.x + fmaxf(p2.y + acc1[nt][1], 0.f) * w2v.y;
            z3 += fmaxf(p3.x + acc1[nt][2], 0.f) * w2v.x + fmaxf(p3.y + acc1[nt][3], 0.f) * w2v.y;
        }
        z0 += __shfl_xor_sync(0xffffffffu, z0, 1);
        z0 += __shfl_xor_sync(0xffffffffu, z0, 2);
        z1 += __shfl_xor_sync(0xffffffffu, z1, 1);
        z1 += __shfl_xor_sync(0xffffffffu, z1, 2);
        z2 += __shfl_xor_sync(0xffffffffu, z2, 1);
        z2 += __shfl_xor_sync(0xffffffffu, z2, 2);
        z3 += __shfl_xor_sync(0xffffffffu, z3, 1);
        z3 += __shfl_xor_sync(0xffffffffu, z3, 2);
        if ((lane & 3) == 0) {
            float* zb = zbuf + zidx + hf * 32 + r0;
            zb[0]  = z0;
            zb[8]  = z1;
            zb[16] = z2;
            zb[24] = z3;
        }
        asm volatile("bar.sync %0, 64;" :: "r"(pair + 1) : "memory");

        // ---- combine halves + sigmoid: lane owns edge `lane` (0..31) ----
        float zz = zbuf[zidx + lane] + zbuf[zidx + 32 + lane] + b2s;
        float wg_l = 1.f / (1.f + __expf(-zz));

        // ---- scatter: this warp's 16 edges ----
        #pragma unroll
        for (int i = 0; i < 16; i++) {
            int ii = 16 * hf + i;
            int s = __shfl_sync(0xffffffffu, vs, ii);
            int t = __shfl_sync(0xffffffffu, vt, ii);
            float wg = __shfl_sync(0xffffffffu, wg_l, ii);
            float4 p = *reinterpret_cast<const float4*>(src + (size_t)s * 128 + 4 * lane);
            float* mr = msg + (size_t)t * 128 + 4 * lane;
            red_add_v4(mr, wg * p.x, wg * p.y, wg * p.z, wg * p.w);
        }

        if (ptn >= NT32) break;
        pt = ptn;
        vs = vs_n;
        vt = vt_n;
    }
}

// ---------------- final: bf16x3 split-precision mma ----------------
#define FI_BHI 0          // bf16 [128][272] -> 34816
#define FI_BLO 34816      // -> 69632
#define FI_AHI 69632      // bf16 [256][272] -> 139264
#define FI_ALO 139264     // -> 208896
#define FI_BS  208896     // 128 floats
#define FI_TOTAL 209408

__global__ __launch_bounds__(512, 1) void final_kernel(
    const float* __restrict__ x_a, const float* __restrict__ x_b,
    const float* __restrict__ Wrel_ab, const float* __restrict__ brel_ab,
    const float* __restrict__ Wroot_ab, const float* __restrict__ broot_ab,
    const float* __restrict__ Wrel_ba, const float* __restrict__ brel_ba,
    const float* __restrict__ Wroot_ba, const float* __restrict__ broot_ba,
    float* __restrict__ out)
{
    extern __shared__ char smc[];
    uint32_t smb = smem_u32(smc);
    float* bsf = (float*)(smc + FI_BS);

    int side = blockIdx.y;
    const float* x     = side ? x_b : x_a;
    const float* msg   = side ? g_msg_b : g_msg_a;
    const float* Wrel  = side ? Wrel_ab  : Wrel_ba;
    const float* brel  = side ? brel_ab  : brel_ba;
    const float* Wroot = side ? Wroot_ab : Wroot_ba;
    const float* broot = side ? broot_ab : broot_ba;
    float* o = out + (size_t)side * NN * DD;

    int tid = threadIdx.x, lane = tid & 31, w = tid >> 5;
    int nbase = blockIdx.x * 256;

    if (tid < 128) bsf[tid] = brel[tid] + broot[tid];

    uint32_t a_lane_off = (uint32_t)(lane & 15) * 272 + (((uint32_t)lane >> 4) << 4);
    uint32_t b_lane_off = (uint32_t)(lane & 7) * 272 + ((((uint32_t)lane >> 3) & 1) << 4);
    uint32_t a_base = smb + FI_AHI + (uint32_t)(16 * w) * 272 + a_lane_off;
    uint32_t a_base_lo = a_base + (FI_ALO - FI_AHI);

    float acc[16][4];
    #pragma unroll
    for (int nt = 0; nt < 16; nt++)
        #pragma unroll
        for (int q = 0; q < 4; q++) acc[nt][q] = 0.f;

    for (int term = 0; term < 2; term++) {
        const float* Asrc = term ? x : msg;
        const float* Bsrc = term ? Wroot : Wrel;
        if (term) __syncthreads();

        for (int idx = tid; idx < 128 * 64; idx += 512) {
            int i = idx >> 6, cp = idx & 63;
            float2 v = *reinterpret_cast<const float2*>(Bsrc + i * 128 + cp * 2);
            __nv_bfloat162 h = __floats2bfloat162_rn(v.x, v.y);
            float2 hf = __bfloat1622float2(h);
            __nv_bfloat162 l = __floats2bfloat162_rn(v.x - hf.x, v.y - hf.y);
            *(uint32_t*)(smc + FI_BHI + i * 272 + cp * 4) = bf2u(h);
            *(uint32_t*)(smc + FI_BLO + i * 272 + cp * 4) = bf2u(l);
        }
        for (int idx = tid; idx < 256 * 32; idx += 512) {
            int row = idx >> 5, cp = idx & 31;
            int n = nbase + row;
            float4 v = make_float4(0.f, 0.f, 0.f, 0.f);
            if (n < NN) v = *reinterpret_cast<const float4*>(Asrc + (size_t)n * 128 + cp * 4);
            __nv_bfloat162 h0 = __floats2bfloat162_rn(v.x, v.y);
            __nv_bfloat162 h1 = __floats2bfloat162_rn(v.z, v.w);
            float2 f0 = __bfloat1622float2(h0);
            float2 f1 = __bfloat1622float2(h1);
            uint2 ph, pl;
            ph.x = bf2u(h0);
            ph.y = bf2u(h1);
            pl.x = bf2u(__floats2bfloat162_rn(v.x - f0.x, v.y - f0.y));
            pl.y = bf2u(__floats2bfloat162_rn(v.z - f1.x, v.w - f1.y));
            *reinterpret_cast<uint2*>(smc + FI_AHI + row * 272 + cp * 8) = ph;
            *reinterpret_cast<uint2*>(smc + FI_ALO + row * 272 + cp * 8) = pl;
        }
        __syncthreads();

        mma_rows16(a_base,    smb + FI_BHI + b_lane_off, acc);
        mma_rows16(a_base,    smb + FI_BLO + b_lane_off, acc);
        mma_rows16(a_base_lo, smb + FI_BHI + b_lane_off, acc);
    }

    int r0 = 16 * w + (lane >> 2), r1 = r0 + 8;
    int cq = (lane & 3) * 2;
    int n0 = nbase + r0, n1 = nbase + r1;
    #pragma unroll
    for (int nt = 0; nt < 16; nt++) {
        int c = nt * 8 + cq;
        float2 bb = *reinterpret_cast<const float2*>(bsf + c);
        if (n0 < NN) {
            float2 v = make_float2(acc[nt][0] + bb.x, acc[nt][1] + bb.y);
            *reinterpret_cast<float2*>(o + (size_t)n0 * 128 + c) = v;
        }
        if (n1 < NN) {
            float2 v = make_float2(acc[nt][2] + bb.x, acc[nt][3] + bb.y);
            *reinterpret_cast<float2*>(o + (size_t)n1 * 128 + c) = v;
        }
    }
}

// ---------------- host ----------------
extern "C" void kernel_launch(void* const* d_in, const int* in_sizes, int n_in,
                              void* d_out, int out_size)
{
    const float* x_a = (const float*)d_in[0];
    const float* x_b = (const float*)d_in[1];
    const float* Wp  = (const float*)d_in[2];
    const float* bp  = (const float*)d_in[3];
    const float* Wc  = (const float*)d_in[4];
    const float* bc  = (const float*)d_in[5];
    const float* W1  = (const float*)d_in[6];
    const float* b1  = (const float*)d_in[7];
    const float* W2  = (const float*)d_in[8];
    const float* b2  = (const float*)d_in[9];
    const float* Wrel_ab  = (const float*)d_in[10];
    const float* brel_ab  = (const float*)d_in[11];
    const float* Wroot_ab = (const float*)d_in[12];
    const float* broot_ab = (const float*)d_in[13];
    const float* Wrel_ba  = (const float*)d_in[14];
    const float* brel_ba  = (const float*)d_in[15];
    const float* Wroot_ba = (const float*)d_in[16];
    const float* broot_ba = (const float*)d_in[17];
    const int* ei_ab = (const int*)d_in[18];
    const int* ei_ba = (const int*)d_in[19];
    float* out = (float*)d_out;

    cudaFuncSetAttribute(node_pre_kernel, cudaFuncAttributeMaxDynamicSharedMemorySize, NP_TOTAL);
    cudaFuncSetAttribute(edge_mma_kernel, cudaFuncAttributeMaxDynamicSharedMemorySize, EP_TOTAL);
    cudaFuncSetAttribute(final_kernel,    cudaFuncAttributeMaxDynamicSharedMemorySize, FI_TOTAL);

    zero_cvt_kernel<<<(NN * DD / 4 + 255) / 256, 256>>>(x_a, x_b);
    node_pre_kernel<<<dim3((NN + 255) / 256, 2), 512, NP_TOTAL>>>(x_a, x_b, Wp, bp, Wc, bc, W1, b1);
    edge_mma_kernel<<<296, 256, EP_TOTAL>>>(x_a, x_b, ei_ab, W1, W2, b2, 0);
    edge_mma_kernel<<<296, 256, EP_TOTAL>>>(x_a, x_b, ei_ba, W1, W2, b2, 1);
    final_kernel<<<dim3((NN + 255) / 256, 2), 512, FI_TOTAL>>>(
        x_a, x_b, Wrel_ab, brel_ab, Wroot_ab, broot_ab,
        Wrel_ba, brel_ba, Wroot_ba, broot_ba, out);
}

// round 13
// speedup vs baseline: 1.0358x; 1.0358x over previous
#include <cuda_runtime.h>
#include <cuda_bf16.h>
#include <math.h>
#include <stdint.h>

#define NN 50000
#define DD 128
#define EE 500000
#define NWT (EE / 16)    // 31250 pair-tiles, exact

// ---------------- device scratch ----------------
static __device__ __nv_bfloat16 g_A1a[NN*DD];   // lrelu(x_a@Wp.T+bp)@W1p.T + b1
static __device__ __nv_bfloat16 g_C1a[NN*DD];   // lrelu(x_a@Wc.T+bc)@W1c.T
static __device__ __nv_bfloat16 g_A1b[NN*DD];
static __device__ __nv_bfloat16 g_C1b[NN*DD];
static __device__ __nv_bfloat16 g_xa16[NN*DD];  // bf16 copies of x (gather path)
static __device__ __nv_bfloat16 g_xb16[NN*DD];
static __device__ float g_msg_a[NN*DD];
static __device__ float g_msg_b[NN*DD];

__device__ __forceinline__ uint32_t smem_u32(const void* p) {
    uint32_t a;
    asm("{ .reg .u64 t; cvta.to.shared.u64 t, %1; cvt.u32.u64 %0, t; }" : "=r"(a) : "l"(p));
    return a;
}
__device__ __forceinline__ void ldsm_x4(uint32_t* r, uint32_t addr) {
    asm volatile("ldmatrix.sync.aligned.m8n8.x4.shared.b16 {%0,%1,%2,%3}, [%4];"
                 : "=r"(r[0]), "=r"(r[1]), "=r"(r[2]), "=r"(r[3]) : "r"(addr));
}
__device__ __forceinline__ void ldsm_x2(uint32_t* r, uint32_t addr) {
    asm volatile("ldmatrix.sync.aligned.m8n8.x2.shared.b16 {%0,%1}, [%2];"
                 : "=r"(r[0]), "=r"(r[1]) : "r"(addr));
}
__device__ __forceinline__ void mma_bf16(float* c, const uint32_t* a, const uint32_t* b) {
    asm volatile("mma.sync.aligned.m16n8k16.row.col.f32.bf16.bf16.f32 "
                 "{%0,%1,%2,%3}, {%4,%5,%6,%7}, {%8,%9}, {%0,%1,%2,%3};"
                 : "+f"(c[0]), "+f"(c[1]), "+f"(c[2]), "+f"(c[3])
                 : "r"(a[0]), "r"(a[1]), "r"(a[2]), "r"(a[3]), "r"(b[0]), "r"(b[1]));
}
__device__ __forceinline__ void red_add_v4(float* p, float a, float b, float c, float d) {
    asm volatile("red.global.add.v4.f32 [%0], {%1, %2, %3, %4};"
                 :: "l"(p), "f"(a), "f"(b), "f"(c), "f"(d) : "memory");
}
__device__ __forceinline__ __nv_bfloat162 u2bf2(uint32_t u) {
    return *reinterpret_cast<__nv_bfloat162*>(&u);
}
__device__ __forceinline__ uint32_t bf2u(__nv_bfloat162 h) {
    return *reinterpret_cast<uint32_t*>(&h);
}

// 16-row x 128-col x K=128 warp MMA over stride-272 bf16 smem tiles; accumulates.
__device__ __forceinline__ void mma_rows16(uint32_t a_addr0, uint32_t b_base, float acc[16][4]) {
    #pragma unroll
    for (int k = 0; k < 8; k++) {
        uint32_t afrag[4];
        ldsm_x4(afrag, a_addr0 + k * 32);
        uint32_t bb = b_base + k * 32;
        #pragma unroll
        for (int nt = 0; nt < 16; nt++) {
            uint32_t bfrag[2];
            ldsm_x2(bfrag, bb + nt * 2176);
            mma_bf16(acc[nt], afrag, bfrag);
        }
    }
}

// ---------------- zero msg + make bf16 x copies ----------------
__global__ void zero_cvt_kernel(const float* __restrict__ xa, const float* __restrict__ xb) {
    int i = blockIdx.x * blockDim.x + threadIdx.x;
    if (i < NN * DD / 4) {
        float4 z = make_float4(0.f, 0.f, 0.f, 0.f);
        reinterpret_cast<float4*>(g_msg_a)[i] = z;
        reinterpret_cast<float4*>(g_msg_b)[i] = z;
        float4 a = reinterpret_cast<const float4*>(xa)[i];
        float4 b = reinterpret_cast<const float4*>(xb)[i];
        uint2 pa, pb;
        pa.x = bf2u(__floats2bfloat162_rn(a.x, a.y));
        pa.y = bf2u(__floats2bfloat162_rn(a.z, a.w));
        pb.x = bf2u(__floats2bfloat162_rn(b.x, b.y));
        pb.y = bf2u(__floats2bfloat162_rn(b.z, b.w));
        reinterpret_cast<uint2*>(g_xa16)[i] = pa;
        reinterpret_cast<uint2*>(g_xb16)[i] = pb;
    }
}

// ---------------- node precompute: merged chains per side ----------------
#define NP_WT   0         // bf16 [128][272] -> 34816
#define NP_UT   34816     // bf16 [128][272] -> 69632
#define NP_XS   69632     // bf16 [256][272] -> 139264
#define NP_TS   139264    // bf16 [256][272] -> 208896
#define NP_BENC 208896    // 2 x 128 floats (bp, bc)
#define NP_B1   209920    // 128 floats
#define NP_TOTAL 210432

__global__ __launch_bounds__(512, 1) void node_pre_kernel(
    const float* __restrict__ x_a, const float* __restrict__ x_b,
    const float* __restrict__ Wp, const float* __restrict__ bp,
    const float* __restrict__ Wc, const float* __restrict__ bc,
    const float* __restrict__ W1, const float* __restrict__ b1)
{
    extern __shared__ char smc[];
    uint32_t smb = smem_u32(smc);
    float* benc = (float*)(smc + NP_BENC);
    float* b1sm = (float*)(smc + NP_B1);

    int sidex = blockIdx.y;
    const float* X = sidex ? x_b : x_a;
    __nv_bfloat16* OutA = sidex ? g_A1b : g_A1a;
    __nv_bfloat16* OutC = sidex ? g_C1b : g_C1a;

    int tid = threadIdx.x, lane = tid & 31, w = tid >> 5;
    int nbase = blockIdx.x * 256;

    for (int idx = tid; idx < 256 * 32; idx += 512) {
        int row = idx >> 5, cp = idx & 31;
        int n = nbase + row;
        float4 f = make_float4(0.f, 0.f, 0.f, 0.f);
        if (n < NN) f = *reinterpret_cast<const float4*>(X + (size_t)n * 128 + cp * 4);
        uint2 pk;
        pk.x = bf2u(__floats2bfloat162_rn(f.x, f.y));
        pk.y = bf2u(__floats2bfloat162_rn(f.z, f.w));
        *reinterpret_cast<uint2*>(smc + NP_XS + row * 272 + cp * 8) = pk;
    }
    if (tid < 128) {
        benc[tid]       = bp[tid];
        benc[128 + tid] = bc[tid];
        b1sm[tid]       = b1[tid];
    }

    uint32_t a_lane_off = (uint32_t)(lane & 15) * 272 + (((uint32_t)lane >> 4) << 4);
    uint32_t b_lane_off = (uint32_t)(lane & 7) * 272 + ((((uint32_t)lane >> 3) & 1) << 4);
    int r0 = 16 * w + (lane >> 2), r1 = r0 + 8;
    int cq = (lane & 3) * 2;
    int n0 = nbase + r0, n1 = nbase + r1;

    for (int cc = 0; cc < 2; cc++) {
        const float* W = cc ? Wc : Wp;
        int off = cc ? 128 : 0;
        __nv_bfloat16* Out = cc ? OutC : OutA;

        for (int idx = tid; idx < 128 * 64; idx += 512) {
            int i = idx >> 6, cp = idx & 63;
            float2 fw = *reinterpret_cast<const float2*>(W + i * 128 + cp * 2);
            float2 fu = *reinterpret_cast<const float2*>(W1 + i * 384 + off + cp * 2);
            *(uint32_t*)(smc + NP_WT + i * 272 + cp * 4) = bf2u(__floats2bfloat162_rn(fw.x, fw.y));
            *(uint32_t*)(smc + NP_UT + i * 272 + cp * 4) = bf2u(__floats2bfloat162_rn(fu.x, fu.y));
        }
        __syncthreads();

        float acc[16][4];
        #pragma unroll
        for (int nt = 0; nt < 16; nt++)
            #pragma unroll
            for (int q = 0; q < 4; q++) acc[nt][q] = 0.f;
        mma_rows16(smb + NP_XS + (uint32_t)(16 * w) * 272 + a_lane_off, smb + NP_WT + b_lane_off, acc);

        #pragma unroll
        for (int nt = 0; nt < 16; nt++) {
            int c = nt * 8 + cq;
            float2 bb = *reinterpret_cast<const float2*>(benc + cc * 128 + c);
            float v0 = acc[nt][0] + bb.x, v1 = acc[nt][1] + bb.y;
            float v2 = acc[nt][2] + bb.x, v3 = acc[nt][3] + bb.y;
            v0 = v0 > 0.f ? v0 : 0.01f * v0;
            v1 = v1 > 0.f ? v1 : 0.01f * v1;
            v2 = v2 > 0.f ? v2 : 0.01f * v2;
            v3 = v3 > 0.f ? v3 : 0.01f * v3;
            *(uint32_t*)(smc + NP_TS + r0 * 272 + c * 2) = bf2u(__floats2bfloat162_rn(v0, v1));
            *(uint32_t*)(smc + NP_TS + r1 * 272 + c * 2) = bf2u(__floats2bfloat162_rn(v2, v3));
        }
        __syncwarp();

        #pragma unroll
        for (int nt = 0; nt < 16; nt++)
            #pragma unroll
            for (int q = 0; q < 4; q++) acc[nt][q] = 0.f;
        mma_rows16(smb + NP_TS + (uint32_t)(16 * w) * 272 + a_lane_off, smb + NP_UT + b_lane_off, acc);

        #pragma unroll
        for (int nt = 0; nt < 16; nt++) {
            int c = nt * 8 + cq;
            float bx = (cc == 0) ? b1sm[c] : 0.f;
            float by = (cc == 0) ? b1sm[c + 1] : 0.f;
            uint32_t h0 = bf2u(__floats2bfloat162_rn(acc[nt][0] + bx, acc[nt][1] + by));
            uint32_t h1 = bf2u(__floats2bfloat162_rn(acc[nt][2] + bx, acc[nt][3] + by));
            if (n0 < NN) *(uint32_t*)(Out + (size_t)n0 * 128 + c) = h0;
            if (n1 < NN) *(uint32_t*)(Out + (size_t)n1 * 128 + c) = h1;
        }
        __syncthreads();
    }
}

// ---------------- edge kernel: warp-pair tiles + register-staged gather/scatter ----------------
#define EP_W2   0          // 128 floats -> 512
#define EP_W1D  512        // bf16 [128][272] -> 35328
#define EP_DIFF 35328      // 4 pairs x 16x272 -> 52736
#define EP_PRES 52736      // 4 pairs x 16x272 -> 70144
#define EP_ZB   70144      // 4 pairs x 32 floats -> 70656
#define EP_TOTAL 70656

__global__ __launch_bounds__(256, 2) void edge_mma_kernel(
    const float* __restrict__ x_a, const float* __restrict__ x_b,
    const int* __restrict__ ei,
    const float* __restrict__ W1,
    const float* __restrict__ W2, const float* __restrict__ b2,
    int side)
{
    extern __shared__ char smc[];
    uint32_t smb = smem_u32(smc);
    float* w2s  = (float*)(smc + EP_W2);
    float* zbuf = (float*)(smc + EP_ZB);

    const float* src = side ? x_b : x_a;                     // fp32, scatter only
    const __nv_bfloat16* s16 = side ? g_xb16 : g_xa16;
    const __nv_bfloat16* d16 = side ? g_xa16 : g_xb16;
    const __nv_bfloat16* A1 = side ? g_A1b : g_A1a;
    const __nv_bfloat16* C1 = side ? g_C1a : g_C1b;
    float* msg              = side ? g_msg_a : g_msg_b;

    int tid = threadIdx.x, lane = tid & 31, w = tid >> 5;
    int pair = w >> 1, hf = w & 1;

    for (int idx = tid; idx < 128 * 64; idx += 256) {
        int i = idx >> 6, cp = idx & 63;
        float2 f = *reinterpret_cast<const float2*>(W1 + i * 384 + 256 + cp * 2);
        *(uint32_t*)(smc + EP_W1D + i * 272 + cp * 4) = bf2u(__floats2bfloat162_rn(f.x, f.y));
    }
    if (tid < 128) w2s[tid] = W2[tid];
    float b2s = __ldg(b2);
    __syncthreads();

    uint32_t tile_off = (uint32_t)pair * 4352;
    uint32_t a_addr0 = smb + EP_DIFF + tile_off + (uint32_t)(lane & 15) * 272 + (((uint32_t)lane >> 4) << 4);
    uint32_t b_base  = smb + EP_W1D + (uint32_t)(lane & 7) * 272 + ((((uint32_t)lane >> 3) & 1) << 4)
                     + (uint32_t)hf * (8 * 2176);
    int r0 = lane >> 2, r1 = r0 + 8;      // rows within the pair tile
    int cq = (lane & 3) * 2;
    int chf = hf * 64;
    int li16 = lane & 15;
    int isdst = lane >> 4;
    int zidx = pair * 32;

    const int pstride = gridDim.x * 4;
    int pt = blockIdx.x * 4 + pair;
    if (pt >= NWT) return;

    int vidx = __ldg(ei + isdst * EE + pt * 16 + li16);

    while (true) {
        // ---- register-staged gather: all 32 loads in flight before processing ----
        uint2 pu[8], cu[8], a1r[8], c1r[8];
        #pragma unroll
        for (int i = 0; i < 8; i++) {
            int ii = 8 * hf + i;
            int s = __shfl_sync(0xffffffffu, vidx, ii);
            int t = __shfl_sync(0xffffffffu, vidx, 16 + ii);
            pu[i]  = *reinterpret_cast<const uint2*>(s16 + (size_t)s * 128 + 4 * lane);
            cu[i]  = *reinterpret_cast<const uint2*>(d16 + (size_t)t * 128 + 4 * lane);
            a1r[i] = *reinterpret_cast<const uint2*>(A1  + (size_t)s * 128 + 4 * lane);
            c1r[i] = *reinterpret_cast<const uint2*>(C1  + (size_t)t * 128 + 4 * lane);
        }
        #pragma unroll
        for (int i = 0; i < 8; i++) {
            int ii = 8 * hf + i;
            uint2 dpk, ppk;
            dpk.x = bf2u(__habs2(__hsub2(u2bf2(pu[i].x), u2bf2(cu[i].x))));
            dpk.y = bf2u(__habs2(__hsub2(u2bf2(pu[i].y), u2bf2(cu[i].y))));
            ppk.x = bf2u(__hadd2(u2bf2(a1r[i].x), u2bf2(c1r[i].x)));
            ppk.y = bf2u(__hadd2(u2bf2(a1r[i].y), u2bf2(c1r[i].y)));
            *reinterpret_cast<uint2*>(smc + EP_DIFF + tile_off + ii * 272 + lane * 8) = dpk;
            *reinterpret_cast<uint2*>(smc + EP_PRES + tile_off + ii * 272 + lane * 8) = ppk;
        }
        asm volatile("bar.sync %0, 64;" :: "r"(pair + 1) : "memory");

        // ---- prefetch next pair-tile's indices ----
        int ptn = pt + pstride;
        int vnext = 0;
        if (ptn < NWT) vnext = __ldg(ei + isdst * EE + ptn * 16 + li16);

        // ---- mma: this warp's 8 n-tiles (64 cols) over the shared 16 rows ----
        float acc[8][4];
        #pragma unroll
        for (int nt = 0; nt < 8; nt++)
            #pragma unroll
            for (int q = 0; q < 4; q++) acc[nt][q] = 0.f;
        #pragma unroll
        for (int k = 0; k < 8; k++) {
            uint32_t afrag[4];
            ldsm_x4(afrag, a_addr0 + k * 32);
            uint32_t bb = b_base + k * 32;
            #pragma unroll
            for (int nt = 0; nt < 8; nt++) {
                uint32_t bfrag[2];
                ldsm_x2(bfrag, bb + nt * 2176);
                mma_bf16(acc[nt], afrag, bfrag);
            }
        }

        // ---- epilogue: partial z over this warp's 64 cols ----
        float z0 = 0.f, z1 = 0.f;
        #pragma unroll
        for (int nt = 0; nt < 8; nt++) {
            int c = chf + nt * 8 + cq;
            float2 p0 = __bfloat1622float2(*reinterpret_cast<const __nv_bfloat162*>(smc + EP_PRES + tile_off + r0 * 272 + c * 2));
            float2 p1 = __bfloat1622float2(*reinterpret_cast<const __nv_bfloat162*>(smc + EP_PRES + tile_off + r1 * 272 + c * 2));
            float2 w2v = *reinterpret_cast<const float2*>(w2s + c);
            z0 += fmaxf(p0.x + acc[nt][0], 0.f) * w2v.x + fmaxf(p0.y + acc[nt][1], 0.f) * w2v.y;
            z1 += fmaxf(p1.x + acc[nt][2], 0.f) * w2v.x + fmaxf(p1.y + acc[nt][3], 0.f) * w2v.y;
        }
        z0 += __shfl_xor_sync(0xffffffffu, z0, 1);
        z0 += __shfl_xor_sync(0xffffffffu, z0, 2);
        z1 += __shfl_xor_sync(0xffffffffu, z1, 1);
        z1 += __shfl_xor_sync(0xffffffffu, z1, 2);
        if ((lane & 3) == 0) {
            zbuf[zidx + hf * 16 + r0] = z0;
            zbuf[zidx + hf * 16 + r1] = z1;
        }
        asm volatile("bar.sync %0, 64;" :: "r"(pair + 1) : "memory");

        // ---- combine halves + sigmoid (lanes 0-15 own edge `lane`) ----
        float wg_l = 0.f;
        if (lane < 16) {
            float zz = zbuf[zidx + lane] + zbuf[zidx + 16 + lane] + b2s;
            wg_l = 1.f / (1.f + __expf(-zz));
        }

        // ---- register-staged scatter: all 8 src rows in flight, then reds ----
        float4 ps[8];
        #pragma unroll
        for (int i = 0; i < 8; i++) {
            int ii = 8 * hf + i;
            int s = __shfl_sync(0xffffffffu, vidx, ii);
            ps[i] = *reinterpret_cast<const float4*>(src + (size_t)s * 128 + 4 * lane);
        }
        #pragma unroll
        for (int i = 0; i < 8; i++) {
            int ii = 8 * hf + i;
            int t = __shfl_sync(0xffffffffu, vidx, 16 + ii);
            float wg = __shfl_sync(0xffffffffu, wg_l, ii);
            float* mr = msg + (size_t)t * 128 + 4 * lane;
            red_add_v4(mr, wg * ps[i].x, wg * ps[i].y, wg * ps[i].z, wg * ps[i].w);
        }

        if (ptn >= NWT) break;
        pt = ptn;
        vidx = vnext;
    }
}

// ---------------- final: bf16x3 split-precision mma ----------------
#define FI_BHI 0          // bf16 [128][272] -> 34816
#define FI_BLO 34816      // -> 69632
#define FI_AHI 69632      // bf16 [256][272] -> 139264
#define FI_ALO 139264     // -> 208896
#define FI_BS  208896     // 128 floats
#define FI_TOTAL 209408

__global__ __launch_bounds__(512, 1) void final_kernel(
    const float* __restrict__ x_a, const float* __restrict__ x_b,
    const float* __restrict__ Wrel_ab, const float* __restrict__ brel_ab,
    const float* __restrict__ Wroot_ab, const float* __restrict__ broot_ab,
    const float* __restrict__ Wrel_ba, const float* __restrict__ brel_ba,
    const float* __restrict__ Wroot_ba, const float* __restrict__ broot_ba,
    float* __restrict__ out)
{
    extern __shared__ char smc[];
    uint32_t smb = smem_u32(smc);
    float* bsf = (float*)(smc + FI_BS);

    int side = blockIdx.y;
    const float* x     = side ? x_b : x_a;
    const float* msg   = side ? g_msg_b : g_msg_a;
    const float* Wrel  = side ? Wrel_ab  : Wrel_ba;
    const float* brel  = side ? brel_ab  : brel_ba;
    const float* Wroot = side ? Wroot_ab : Wroot_ba;
    const float* broot = side ? broot_ab : broot_ba;
    float* o = out + (size_t)side * NN * DD;

    int tid = threadIdx.x, lane = tid & 31, w = tid >> 5;
    int nbase = blockIdx.x * 256;

    if (tid < 128) bsf[tid] = brel[tid] + broot[tid];

    uint32_t a_lane_off = (uint32_t)(lane & 15) * 272 + (((uint32_t)lane >> 4) << 4);
    uint32_t b_lane_off = (uint32_t)(lane & 7) * 272 + ((((uint32_t)lane >> 3) & 1) << 4);
    uint32_t a_base = smb + FI_AHI + (uint32_t)(16 * w) * 272 + a_lane_off;
    uint32_t a_base_lo = a_base + (FI_ALO - FI_AHI);

    float acc[16][4];
    #pragma unroll
    for (int nt = 0; nt < 16; nt++)
        #pragma unroll
        for (int q = 0; q < 4; q++) acc[nt][q] = 0.f;

    for (int term = 0; term < 2; term++) {
        const float* Asrc = term ? x : msg;
        const float* Bsrc = term ? Wroot : Wrel;
        if (term) __syncthreads();

        for (int idx = tid; idx < 128 * 64; idx += 512) {
            int i = idx >> 6, cp = idx & 63;
            float2 v = *reinterpret_cast<const float2*>(Bsrc + i * 128 + cp * 2);
            __nv_bfloat162 h = __floats2bfloat162_rn(v.x, v.y);
            float2 hf = __bfloat1622float2(h);
            __nv_bfloat162 l = __floats2bfloat162_rn(v.x - hf.x, v.y - hf.y);
            *(uint32_t*)(smc + FI_BHI + i * 272 + cp * 4) = bf2u(h);
            *(uint32_t*)(smc + FI_BLO + i * 272 + cp * 4) = bf2u(l);
        }
        for (int idx = tid; idx < 256 * 32; idx += 512) {
            int row = idx >> 5, cp = idx & 31;
            int n = nbase + row;
            float4 v = make_float4(0.f, 0.f, 0.f, 0.f);
            if (n < NN) v = *reinterpret_cast<const float4*>(Asrc + (size_t)n * 128 + cp * 4);
            __nv_bfloat162 h0 = __floats2bfloat162_rn(v.x, v.y);
            __nv_bfloat162 h1 = __floats2bfloat162_rn(v.z, v.w);
            float2 f0 = __bfloat1622float2(h0);
            float2 f1 = __bfloat1622float2(h1);
            uint2 ph, pl;
            ph.x = bf2u(h0);
            ph.y = bf2u(h1);
            pl.x = bf2u(__floats2bfloat162_rn(v.x - f0.x, v.y - f0.y));
            pl.y = bf2u(__floats2bfloat162_rn(v.z - f1.x, v.w - f1.y));
            *reinterpret_cast<uint2*>(smc + FI_AHI + row * 272 + cp * 8) = ph;
            *reinterpret_cast<uint2*>(smc + FI_ALO + row * 272 + cp * 8) = pl;
        }
        __syncthreads();

        mma_rows16(a_base,    smb + FI_BHI + b_lane_off, acc);
        mma_rows16(a_base,    smb + FI_BLO + b_lane_off, acc);
        mma_rows16(a_base_lo, smb + FI_BHI + b_lane_off, acc);
    }

    int r0 = 16 * w + (lane >> 2), r1 = r0 + 8;
    int cq = (lane & 3) * 2;
    int n0 = nbase + r0, n1 = nbase + r1;
    #pragma unroll
    for (int nt = 0; nt < 16; nt++) {
        int c = nt * 8 + cq;
        float2 bb = *reinterpret_cast<const float2*>(bsf + c);
        if (n0 < NN) {
            float2 v = make_float2(acc[nt][0] + bb.x, acc[nt][1] + bb.y);
            *reinterpret_cast<float2*>(o + (size_t)n0 * 128 + c) = v;
        }
        if (n1 < NN) {
            float2 v = make_float2(acc[nt][2] + bb.x, acc[nt][3] + bb.y);
            *reinterpret_cast<float2*>(o + (size_t)n1 * 128 + c) = v;
        }
    }
}

// ---------------- host ----------------
extern "C" void kernel_launch(void* const* d_in, const int* in_sizes, int n_in,
                              void* d_out, int out_size)
{
    const float* x_a = (const float*)d_in[0];
    const float* x_b = (const float*)d_in[1];
    const float* Wp  = (const float*)d_in[2];
    const float* bp  = (const float*)d_in[3];
    const float* Wc  = (const float*)d_in[4];
    const float* bc  = (const float*)d_in[5];
    const float* W1  = (const float*)d_in[6];
    const float* b1  = (const float*)d_in[7];
    const float* W2  = (const float*)d_in[8];
    const float* b2  = (const float*)d_in[9];
    const float* Wrel_ab  = (const float*)d_in[10];
    const float* brel_ab  = (const float*)d_in[11];
    const float* Wroot_ab = (const float*)d_in[12];
    const float* broot_ab = (const float*)d_in[13];
    const float* Wrel_ba  = (const float*)d_in[14];
    const float* brel_ba  = (const float*)d_in[15];
    const float* Wroot_ba = (const float*)d_in[16];
    const float* broot_ba = (const float*)d_in[17];
    const int* ei_ab = (const int*)d_in[18];
    const int* ei_ba = (const int*)d_in[19];
    float* out = (float*)d_out;

    cudaFuncSetAttribute(node_pre_kernel, cudaFuncAttributeMaxDynamicSharedMemorySize, NP_TOTAL);
    cudaFuncSetAttribute(edge_mma_kernel, cudaFuncAttributeMaxDynamicSharedMemorySize, EP_TOTAL);
    cudaFuncSetAttribute(final_kernel,    cudaFuncAttributeMaxDynamicSharedMemorySize, FI_TOTAL);

    zero_cvt_kernel<<<(NN * DD / 4 + 255) / 256, 256>>>(x_a, x_b);
    node_pre_kernel<<<dim3((NN + 255) / 256, 2), 512, NP_TOTAL>>>(x_a, x_b, Wp, bp, Wc, bc, W1, b1);
    edge_mma_kernel<<<296, 256, EP_TOTAL>>>(x_a, x_b, ei_ab, W1, W2, b2, 0);
    edge_mma_kernel<<<296, 256, EP_TOTAL>>>(x_a, x_b, ei_ba, W1, W2, b2, 1);
    final_kernel<<<dim3((NN + 255) / 256, 2), 512, FI_TOTAL>>>(
        x_a, x_b, Wrel_ab, brel_ab, Wroot_ab, broot_ab,
        Wrel_ba, brel_ba, Wroot_ba, broot_ba, out);
}

// round 14
// speedup vs baseline: 1.2072x; 1.1654x over previous
#include <cuda_runtime.h>
#include <cuda_bf16.h>
#include <math.h>
#include <stdint.h>

#define NN 50000
#define DD 128
#define EE 500000
#define NWT (EE / 16)    // 31250 pair-tiles, exact

// ---------------- device scratch ----------------
static __device__ __nv_bfloat16 g_A1a[NN*DD];   // lrelu(x_a@Wp.T+bp)@W1p.T + b1
static __device__ __nv_bfloat16 g_C1a[NN*DD];   // lrelu(x_a@Wc.T+bc)@W1c.T
static __device__ __nv_bfloat16 g_A1b[NN*DD];
static __device__ __nv_bfloat16 g_C1b[NN*DD];
static __device__ __nv_bfloat16 g_xa16[NN*DD];  // bf16 copies of x (gather path)
static __device__ __nv_bfloat16 g_xb16[NN*DD];
static __device__ float g_msg_a[NN*DD];
static __device__ float g_msg_b[NN*DD];

__device__ __forceinline__ uint32_t smem_u32(const void* p) {
    uint32_t a;
    asm("{ .reg .u64 t; cvta.to.shared.u64 t, %1; cvt.u32.u64 %0, t; }" : "=r"(a) : "l"(p));
    return a;
}
__device__ __forceinline__ void ldsm_x4(uint32_t* r, uint32_t addr) {
    asm volatile("ldmatrix.sync.aligned.m8n8.x4.shared.b16 {%0,%1,%2,%3}, [%4];"
                 : "=r"(r[0]), "=r"(r[1]), "=r"(r[2]), "=r"(r[3]) : "r"(addr));
}
__device__ __forceinline__ void ldsm_x2(uint32_t* r, uint32_t addr) {
    asm volatile("ldmatrix.sync.aligned.m8n8.x2.shared.b16 {%0,%1}, [%2];"
                 : "=r"(r[0]), "=r"(r[1]) : "r"(addr));
}
__device__ __forceinline__ void mma_bf16(float* c, const uint32_t* a, const uint32_t* b) {
    asm volatile("mma.sync.aligned.m16n8k16.row.col.f32.bf16.bf16.f32 "
                 "{%0,%1,%2,%3}, {%4,%5,%6,%7}, {%8,%9}, {%0,%1,%2,%3};"
                 : "+f"(c[0]), "+f"(c[1]), "+f"(c[2]), "+f"(c[3])
                 : "r"(a[0]), "r"(a[1]), "r"(a[2]), "r"(a[3]), "r"(b[0]), "r"(b[1]));
}
__device__ __forceinline__ void mma_tf32(float* c, const uint32_t* a, const uint32_t* b) {
    asm volatile("mma.sync.aligned.m16n8k8.row.col.f32.tf32.tf32.f32 "
                 "{%0,%1,%2,%3}, {%4,%5,%6,%7}, {%8,%9}, {%0,%1,%2,%3};"
                 : "+f"(c[0]), "+f"(c[1]), "+f"(c[2]), "+f"(c[3])
                 : "r"(a[0]), "r"(a[1]), "r"(a[2]), "r"(a[3]), "r"(b[0]), "r"(b[1]));
}
__device__ __forceinline__ uint32_t f2tf32(float f) {
    uint32_t r;
    asm("cvt.rna.tf32.f32 %0, %1;" : "=r"(r) : "f"(f));
    return r;
}
__device__ __forceinline__ void red_add_v4(float* p, float a, float b, float c, float d) {
    asm volatile("red.global.add.v4.f32 [%0], {%1, %2, %3, %4};"
                 :: "l"(p), "f"(a), "f"(b), "f"(c), "f"(d) : "memory");
}
__device__ __forceinline__ __nv_bfloat162 u2bf2(uint32_t u) {
    return *reinterpret_cast<__nv_bfloat162*>(&u);
}
__device__ __forceinline__ uint32_t bf2u(__nv_bfloat162 h) {
    return *reinterpret_cast<uint32_t*>(&h);
}

// 16-row x 128-col x K=128 warp MMA over stride-272 bf16 smem tiles; accumulates.
__device__ __forceinline__ void mma_rows16(uint32_t a_addr0, uint32_t b_base, float acc[16][4]) {
    #pragma unroll
    for (int k = 0; k < 8; k++) {
        uint32_t afrag[4];
        ldsm_x4(afrag, a_addr0 + k * 32);
        uint32_t bb = b_base + k * 32;
        #pragma unroll
        for (int nt = 0; nt < 16; nt++) {
            uint32_t bfrag[2];
            ldsm_x2(bfrag, bb + nt * 2176);
            mma_bf16(acc[nt], afrag, bfrag);
        }
    }
}

// ---------------- zero msg + make bf16 x copies ----------------
__global__ void zero_cvt_kernel(const float* __restrict__ xa, const float* __restrict__ xb) {
    int i = blockIdx.x * blockDim.x + threadIdx.x;
    if (i < NN * DD / 4) {
        float4 z = make_float4(0.f, 0.f, 0.f, 0.f);
        reinterpret_cast<float4*>(g_msg_a)[i] = z;
        reinterpret_cast<float4*>(g_msg_b)[i] = z;
        float4 a = reinterpret_cast<const float4*>(xa)[i];
        float4 b = reinterpret_cast<const float4*>(xb)[i];
        uint2 pa, pb;
        pa.x = bf2u(__floats2bfloat162_rn(a.x, a.y));
        pa.y = bf2u(__floats2bfloat162_rn(a.z, a.w));
        pb.x = bf2u(__floats2bfloat162_rn(b.x, b.y));
        pb.y = bf2u(__floats2bfloat162_rn(b.z, b.w));
        reinterpret_cast<uint2*>(g_xa16)[i] = pa;
        reinterpret_cast<uint2*>(g_xb16)[i] = pb;
    }
}

// ---------------- node precompute: merged chains per side ----------------
#define NP_WT   0         // bf16 [128][272] -> 34816
#define NP_UT   34816     // bf16 [128][272] -> 69632
#define NP_XS   69632     // bf16 [256][272] -> 139264
#define NP_TS   139264    // bf16 [256][272] -> 208896
#define NP_BENC 208896    // 2 x 128 floats (bp, bc)
#define NP_B1   209920    // 128 floats
#define NP_TOTAL 210432

__global__ __launch_bounds__(512, 1) void node_pre_kernel(
    const float* __restrict__ x_a, const float* __restrict__ x_b,
    const float* __restrict__ Wp, const float* __restrict__ bp,
    const float* __restrict__ Wc, const float* __restrict__ bc,
    const float* __restrict__ W1, const float* __restrict__ b1)
{
    extern __shared__ char smc[];
    uint32_t smb = smem_u32(smc);
    float* benc = (float*)(smc + NP_BENC);
    float* b1sm = (float*)(smc + NP_B1);

    int sidex = blockIdx.y;
    const float* X = sidex ? x_b : x_a;
    __nv_bfloat16* OutA = sidex ? g_A1b : g_A1a;
    __nv_bfloat16* OutC = sidex ? g_C1b : g_C1a;

    int tid = threadIdx.x, lane = tid & 31, w = tid >> 5;
    int nbase = blockIdx.x * 256;

    for (int idx = tid; idx < 256 * 32; idx += 512) {
        int row = idx >> 5, cp = idx & 31;
        int n = nbase + row;
        float4 f = make_float4(0.f, 0.f, 0.f, 0.f);
        if (n < NN) f = *reinterpret_cast<const float4*>(X + (size_t)n * 128 + cp * 4);
        uint2 pk;
        pk.x = bf2u(__floats2bfloat162_rn(f.x, f.y));
        pk.y = bf2u(__floats2bfloat162_rn(f.z, f.w));
        *reinterpret_cast<uint2*>(smc + NP_XS + row * 272 + cp * 8) = pk;
    }
    if (tid < 128) {
        benc[tid]       = bp[tid];
        benc[128 + tid] = bc[tid];
        b1sm[tid]       = b1[tid];
    }

    uint32_t a_lane_off = (uint32_t)(lane & 15) * 272 + (((uint32_t)lane >> 4) << 4);
    uint32_t b_lane_off = (uint32_t)(lane & 7) * 272 + ((((uint32_t)lane >> 3) & 1) << 4);
    int r0 = 16 * w + (lane >> 2), r1 = r0 + 8;
    int cq = (lane & 3) * 2;
    int n0 = nbase + r0, n1 = nbase + r1;

    for (int cc = 0; cc < 2; cc++) {
        const float* W = cc ? Wc : Wp;
        int off = cc ? 128 : 0;
        __nv_bfloat16* Out = cc ? OutC : OutA;

        for (int idx = tid; idx < 128 * 64; idx += 512) {
            int i = idx >> 6, cp = idx & 63;
            float2 fw = *reinterpret_cast<const float2*>(W + i * 128 + cp * 2);
            float2 fu = *reinterpret_cast<const float2*>(W1 + i * 384 + off + cp * 2);
            *(uint32_t*)(smc + NP_WT + i * 272 + cp * 4) = bf2u(__floats2bfloat162_rn(fw.x, fw.y));
            *(uint32_t*)(smc + NP_UT + i * 272 + cp * 4) = bf2u(__floats2bfloat162_rn(fu.x, fu.y));
        }
        __syncthreads();

        float acc[16][4];
        #pragma unroll
        for (int nt = 0; nt < 16; nt++)
            #pragma unroll
            for (int q = 0; q < 4; q++) acc[nt][q] = 0.f;
        mma_rows16(smb + NP_XS + (uint32_t)(16 * w) * 272 + a_lane_off, smb + NP_WT + b_lane_off, acc);

        #pragma unroll
        for (int nt = 0; nt < 16; nt++) {
            int c = nt * 8 + cq;
            float2 bb = *reinterpret_cast<const float2*>(benc + cc * 128 + c);
            float v0 = acc[nt][0] + bb.x, v1 = acc[nt][1] + bb.y;
            float v2 = acc[nt][2] + bb.x, v3 = acc[nt][3] + bb.y;
            v0 = v0 > 0.f ? v0 : 0.01f * v0;
            v1 = v1 > 0.f ? v1 : 0.01f * v1;
            v2 = v2 > 0.f ? v2 : 0.01f * v2;
            v3 = v3 > 0.f ? v3 : 0.01f * v3;
            *(uint32_t*)(smc + NP_TS + r0 * 272 + c * 2) = bf2u(__floats2bfloat162_rn(v0, v1));
            *(uint32_t*)(smc + NP_TS + r1 * 272 + c * 2) = bf2u(__floats2bfloat162_rn(v2, v3));
        }
        __syncwarp();

        #pragma unroll
        for (int nt = 0; nt < 16; nt++)
            #pragma unroll
            for (int q = 0; q < 4; q++) acc[nt][q] = 0.f;
        mma_rows16(smb + NP_TS + (uint32_t)(16 * w) * 272 + a_lane_off, smb + NP_UT + b_lane_off, acc);

        #pragma unroll
        for (int nt = 0; nt < 16; nt++) {
            int c = nt * 8 + cq;
            float bx = (cc == 0) ? b1sm[c] : 0.f;
            float by = (cc == 0) ? b1sm[c + 1] : 0.f;
            uint32_t h0 = bf2u(__floats2bfloat162_rn(acc[nt][0] + bx, acc[nt][1] + by));
            uint32_t h1 = bf2u(__floats2bfloat162_rn(acc[nt][2] + bx, acc[nt][3] + by));
            if (n0 < NN) *(uint32_t*)(Out + (size_t)n0 * 128 + c) = h0;
            if (n1 < NN) *(uint32_t*)(Out + (size_t)n1 * 128 + c) = h1;
        }
        __syncthreads();
    }
}

// ---------------- edge kernel: warp-pair tiles + register-staged gather/scatter ----------------
#define EP_W2   0          // 128 floats -> 512
#define EP_W1D  512        // bf16 [128][272] -> 35328
#define EP_DIFF 35328      // 4 pairs x 16x272 -> 52736
#define EP_PRES 52736      // 4 pairs x 16x272 -> 70144
#define EP_ZB   70144      // 4 pairs x 32 floats -> 70656
#define EP_TOTAL 70656

__global__ __launch_bounds__(256, 2) void edge_mma_kernel(
    const float* __restrict__ x_a, const float* __restrict__ x_b,
    const int* __restrict__ ei,
    const float* __restrict__ W1,
    const float* __restrict__ W2, const float* __restrict__ b2,
    int side)
{
    extern __shared__ char smc[];
    uint32_t smb = smem_u32(smc);
    float* w2s  = (float*)(smc + EP_W2);
    float* zbuf = (float*)(smc + EP_ZB);

    const float* src = side ? x_b : x_a;                     // fp32, scatter only
    const __nv_bfloat16* s16 = side ? g_xb16 : g_xa16;
    const __nv_bfloat16* d16 = side ? g_xa16 : g_xb16;
    const __nv_bfloat16* A1 = side ? g_A1b : g_A1a;
    const __nv_bfloat16* C1 = side ? g_C1a : g_C1b;
    float* msg              = side ? g_msg_a : g_msg_b;

    int tid = threadIdx.x, lane = tid & 31, w = tid >> 5;
    int pair = w >> 1, hf = w & 1;

    for (int idx = tid; idx < 128 * 64; idx += 256) {
        int i = idx >> 6, cp = idx & 63;
        float2 f = *reinterpret_cast<const float2*>(W1 + i * 384 + 256 + cp * 2);
        *(uint32_t*)(smc + EP_W1D + i * 272 + cp * 4) = bf2u(__floats2bfloat162_rn(f.x, f.y));
    }
    if (tid < 128) w2s[tid] = W2[tid];
    float b2s = __ldg(b2);
    __syncthreads();

    uint32_t tile_off = (uint32_t)pair * 4352;
    uint32_t a_addr0 = smb + EP_DIFF + tile_off + (uint32_t)(lane & 15) * 272 + (((uint32_t)lane >> 4) << 4);
    uint32_t b_base  = smb + EP_W1D + (uint32_t)(lane & 7) * 272 + ((((uint32_t)lane >> 3) & 1) << 4)
                     + (uint32_t)hf * (8 * 2176);
    int r0 = lane >> 2, r1 = r0 + 8;      // rows within the pair tile
    int cq = (lane & 3) * 2;
    int chf = hf * 64;
    int li16 = lane & 15;
    int isdst = lane >> 4;
    int zidx = pair * 32;

    const int pstride = gridDim.x * 4;
    int pt = blockIdx.x * 4 + pair;
    if (pt >= NWT) return;

    int vidx = __ldg(ei + isdst * EE + pt * 16 + li16);

    while (true) {
        // ---- register-staged gather: all 32 loads in flight before processing ----
        uint2 pu[8], cu[8], a1r[8], c1r[8];
        #pragma unroll
        for (int i = 0; i < 8; i++) {
            int ii = 8 * hf + i;
            int s = __shfl_sync(0xffffffffu, vidx, ii);
            int t = __shfl_sync(0xffffffffu, vidx, 16 + ii);
            pu[i]  = *reinterpret_cast<const uint2*>(s16 + (size_t)s * 128 + 4 * lane);
            cu[i]  = *reinterpret_cast<const uint2*>(d16 + (size_t)t * 128 + 4 * lane);
            a1r[i] = *reinterpret_cast<const uint2*>(A1  + (size_t)s * 128 + 4 * lane);
            c1r[i] = *reinterpret_cast<const uint2*>(C1  + (size_t)t * 128 + 4 * lane);
        }
        #pragma unroll
        for (int i = 0; i < 8; i++) {
            int ii = 8 * hf + i;
            uint2 dpk, ppk;
            dpk.x = bf2u(__habs2(__hsub2(u2bf2(pu[i].x), u2bf2(cu[i].x))));
            dpk.y = bf2u(__habs2(__hsub2(u2bf2(pu[i].y), u2bf2(cu[i].y))));
            ppk.x = bf2u(__hadd2(u2bf2(a1r[i].x), u2bf2(c1r[i].x)));
            ppk.y = bf2u(__hadd2(u2bf2(a1r[i].y), u2bf2(c1r[i].y)));
            *reinterpret_cast<uint2*>(smc + EP_DIFF + tile_off + ii * 272 + lane * 8) = dpk;
            *reinterpret_cast<uint2*>(smc + EP_PRES + tile_off + ii * 272 + lane * 8) = ppk;
        }
        asm volatile("bar.sync %0, 64;" :: "r"(pair + 1) : "memory");

        // ---- prefetch next pair-tile's indices ----
        int ptn = pt + pstride;
        int vnext = 0;
        if (ptn < NWT) vnext = __ldg(ei + isdst * EE + ptn * 16 + li16);

        // ---- mma: this warp's 8 n-tiles (64 cols) over the shared 16 rows ----
        float acc[8][4];
        #pragma unroll
        for (int nt = 0; nt < 8; nt++)
            #pragma unroll
            for (int q = 0; q < 4; q++) acc[nt][q] = 0.f;
        #pragma unroll
        for (int k = 0; k < 8; k++) {
            uint32_t afrag[4];
            ldsm_x4(afrag, a_addr0 + k * 32);
            uint32_t bb = b_base + k * 32;
            #pragma unroll
            for (int nt = 0; nt < 8; nt++) {
                uint32_t bfrag[2];
                ldsm_x2(bfrag, bb + nt * 2176);
                mma_bf16(acc[nt], afrag, bfrag);
            }
        }

        // ---- epilogue: partial z over this warp's 64 cols ----
        float z0 = 0.f, z1 = 0.f;
        #pragma unroll
        for (int nt = 0; nt < 8; nt++) {
            int c = chf + nt * 8 + cq;
            float2 p0 = __bfloat1622float2(*reinterpret_cast<const __nv_bfloat162*>(smc + EP_PRES + tile_off + r0 * 272 + c * 2));
            float2 p1 = __bfloat1622float2(*reinterpret_cast<const __nv_bfloat162*>(smc + EP_PRES + tile_off + r1 * 272 + c * 2));
            float2 w2v = *reinterpret_cast<const float2*>(w2s + c);
            z0 += fmaxf(p0.x + acc[nt][0], 0.f) * w2v.x + fmaxf(p0.y + acc[nt][1], 0.f) * w2v.y;
            z1 += fmaxf(p1.x + acc[nt][2], 0.f) * w2v.x + fmaxf(p1.y + acc[nt][3], 0.f) * w2v.y;
        }
        z0 += __shfl_xor_sync(0xffffffffu, z0, 1);
        z0 += __shfl_xor_sync(0xffffffffu, z0, 2);
        z1 += __shfl_xor_sync(0xffffffffu, z1, 1);
        z1 += __shfl_xor_sync(0xffffffffu, z1, 2);
        if ((lane & 3) == 0) {
            zbuf[zidx + hf * 16 + r0] = z0;
            zbuf[zidx + hf * 16 + r1] = z1;
        }
        asm volatile("bar.sync %0, 64;" :: "r"(pair + 1) : "memory");

        // ---- combine halves + sigmoid (lanes 0-15 own edge `lane`) ----
        float wg_l = 0.f;
        if (lane < 16) {
            float zz = zbuf[zidx + lane] + zbuf[zidx + 16 + lane] + b2s;
            wg_l = 1.f / (1.f + __expf(-zz));
        }

        // ---- register-staged scatter: all 8 src rows in flight, then reds ----
        float4 ps[8];
        #pragma unroll
        for (int i = 0; i < 8; i++) {
            int ii = 8 * hf + i;
            int s = __shfl_sync(0xffffffffu, vidx, ii);
            ps[i] = *reinterpret_cast<const float4*>(src + (size_t)s * 128 + 4 * lane);
        }
        #pragma unroll
        for (int i = 0; i < 8; i++) {
            int ii = 8 * hf + i;
            int t = __shfl_sync(0xffffffffu, vidx, 16 + ii);
            float wg = __shfl_sync(0xffffffffu, wg_l, ii);
            float* mr = msg + (size_t)t * 128 + 4 * lane;
            red_add_v4(mr, wg * ps[i].x, wg * ps[i].y, wg * ps[i].z, wg * ps[i].w);
        }

        if (ptn >= NWT) break;
        pt = ptn;
        vidx = vnext;
    }
}

// ---------------- final: single-pass tf32 mma ----------------
// smem: A [256][132] fp32(tf32) @0 -> 135168; B [128][132] @135168 -> 202752; bias @202752
#define FT_A    0
#define FT_B    135168
#define FT_BS   202752
#define FT_TOTAL 203264

__global__ __launch_bounds__(512, 1) void final_kernel(
    const float* __restrict__ x_a, const float* __restrict__ x_b,
    const float* __restrict__ Wrel_ab, const float* __restrict__ brel_ab,
    const float* __restrict__ Wroot_ab, const float* __restrict__ broot_ab,
    const float* __restrict__ Wrel_ba, const float* __restrict__ brel_ba,
    const float* __restrict__ Wroot_ba, const float* __restrict__ broot_ba,
    float* __restrict__ out)
{
    extern __shared__ char smc[];
    float* bsf = (float*)(smc + FT_BS);

    int side = blockIdx.y;
    const float* x     = side ? x_b : x_a;
    const float* msg   = side ? g_msg_b : g_msg_a;
    const float* Wrel  = side ? Wrel_ab  : Wrel_ba;
    const float* brel  = side ? brel_ab  : brel_ba;
    const float* Wroot = side ? Wroot_ab : Wroot_ba;
    const float* broot = side ? broot_ab : broot_ba;
    float* o = out + (size_t)side * NN * DD;

    int tid = threadIdx.x, lane = tid & 31, w = tid >> 5;
    int nbase = blockIdx.x * 256;

    if (tid < 128) bsf[tid] = brel[tid] + broot[tid];

    // lane-level fragment offsets (bytes), stride 528 = 132 floats
    uint32_t a_lane = (uint32_t)((lane >> 2) * 528 + (lane & 3) * 4);
    uint32_t b_lane = a_lane;   // same pattern for B (n = lane>>2, k = lane&3)

    float acc[16][4];
    #pragma unroll
    for (int nt = 0; nt < 16; nt++)
        #pragma unroll
        for (int q = 0; q < 4; q++) acc[nt][q] = 0.f;

    for (int term = 0; term < 2; term++) {
        const float* Asrc = term ? x : msg;
        const float* Bsrc = term ? Wroot : Wrel;
        if (term) __syncthreads();   // protect term-0 reads before overwrite

        // B fill: [128 n][128 k] fp32 -> tf32, stride 132 floats
        for (int idx = tid; idx < 128 * 64; idx += 512) {
            int i = idx >> 6, cp = idx & 63;
            float2 v = *reinterpret_cast<const float2*>(Bsrc + i * 128 + cp * 2);
            uint2 t;
            t.x = f2tf32(v.x);
            t.y = f2tf32(v.y);
            *reinterpret_cast<uint2*>(smc + FT_B + i * 528 + cp * 8) = t;
        }
        // A fill: [256 rows][128 k] fp32 -> tf32 (guarded)
        for (int idx = tid; idx < 256 * 32; idx += 512) {
            int row = idx >> 5, cp = idx & 31;
            int n = nbase + row;
            float4 v = make_float4(0.f, 0.f, 0.f, 0.f);
            if (n < NN) v = *reinterpret_cast<const float4*>(Asrc + (size_t)n * 128 + cp * 4);
            uint4 t;
            t.x = f2tf32(v.x);
            t.y = f2tf32(v.y);
            t.z = f2tf32(v.z);
            t.w = f2tf32(v.w);
            *reinterpret_cast<uint4*>(smc + FT_A + row * 528 + cp * 16) = t;
        }
        __syncthreads();

        // mma: warp w owns rows 16w..16w+15, all 128 cols; K=128 in 16 steps of 8
        const char* abase = smc + FT_A + (uint32_t)(16 * w) * 528 + a_lane;
        const char* bbase = smc + FT_B + b_lane;
        #pragma unroll
        for (int k = 0; k < 16; k++) {
            uint32_t af[4];
            const char* ak = abase + k * 32;
            af[0] = *(const uint32_t*)(ak);
            af[1] = *(const uint32_t*)(ak + 8 * 528);
            af[2] = *(const uint32_t*)(ak + 16);
            af[3] = *(const uint32_t*)(ak + 8 * 528 + 16);
            const char* bk = bbase + k * 32;
            #pragma unroll
            for (int nt = 0; nt < 16; nt++) {
                uint32_t bf[2];
                const char* bn = bk + nt * 8 * 528;
                bf[0] = *(const uint32_t*)(bn);
                bf[1] = *(const uint32_t*)(bn + 16);
                mma_tf32(acc[nt], af, bf);
            }
        }
    }

    int r0 = 16 * w + (lane >> 2), r1 = r0 + 8;
    int cq = (lane & 3) * 2;
    int n0 = nbase + r0, n1 = nbase + r1;
    #pragma unroll
    for (int nt = 0; nt < 16; nt++) {
        int c = nt * 8 + cq;
        float2 bb = *reinterpret_cast<const float2*>(bsf + c);
        if (n0 < NN) {
            float2 v = make_float2(acc[nt][0] + bb.x, acc[nt][1] + bb.y);
            *reinterpret_cast<float2*>(o + (size_t)n0 * 128 + c) = v;
        }
        if (n1 < NN) {
            float2 v = make_float2(acc[nt][2] + bb.x, acc[nt][3] + bb.y);
            *reinterpret_cast<float2*>(o + (size_t)n1 * 128 + c) = v;
        }
    }
}

// ---------------- host ----------------
extern "C" void kernel_launch(void* const* d_in, const int* in_sizes, int n_in,
                              void* d_out, int out_size)
{
    const float* x_a = (const float*)d_in[0];
    const float* x_b = (const float*)d_in[1];
    const float* Wp  = (const float*)d_in[2];
    const float* bp  = (const float*)d_in[3];
    const float* Wc  = (const float*)d_in[4];
    const float* bc  = (const float*)d_in[5];
    const float* W1  = (const float*)d_in[6];
    const float* b1  = (const float*)d_in[7];
    const float* W2  = (const float*)d_in[8];
    const float* b2  = (const float*)d_in[9];
    const float* Wrel_ab  = (const float*)d_in[10];
    const float* brel_ab  = (const float*)d_in[11];
    const float* Wroot_ab = (const float*)d_in[12];
    const float* broot_ab = (const float*)d_in[13];
    const float* Wrel_ba  = (const float*)d_in[14];
    const float* brel_ba  = (const float*)d_in[15];
    const float* Wroot_ba = (const float*)d_in[16];
    const float* broot_ba = (const float*)d_in[17];
    const int* ei_ab = (const int*)d_in[18];
    const int* ei_ba = (const int*)d_in[19];
    float* out = (float*)d_out;

    cudaFuncSetAttribute(node_pre_kernel, cudaFuncAttributeMaxDynamicSharedMemorySize, NP_TOTAL);
    cudaFuncSetAttribute(edge_mma_kernel, cudaFuncAttributeMaxDynamicSharedMemorySize, EP_TOTAL);
    cudaFuncSetAttribute(final_kernel,    cudaFuncAttributeMaxDynamicSharedMemorySize, FT_TOTAL);

    zero_cvt_kernel<<<(NN * DD / 4 + 255) / 256, 256>>>(x_a, x_b);
    node_pre_kernel<<<dim3((NN + 255) / 256, 2), 512, NP_TOTAL>>>(x_a, x_b, Wp, bp, Wc, bc, W1, b1);
    edge_mma_kernel<<<296, 256, EP_TOTAL>>>(x_a, x_b, ei_ab, W1, W2, b2, 0);
    edge_mma_kernel<<<296, 256, EP_TOTAL>>>(x_a, x_b, ei_ba, W1, W2, b2, 1);
    final_kernel<<<dim3((NN + 255) / 256, 2), 512, FT_TOTAL>>>(
        x_a, x_b, Wrel_ab, brel_ab, Wroot_ab, broot_ab,
        Wrel_ba, brel_ba, Wroot_ba, broot_ba, out);
}

// round 15
// speedup vs baseline: 1.2303x; 1.0192x over previous
#include <cuda_runtime.h>
#include <cuda_bf16.h>
#include <math.h>
#include <stdint.h>

#define NN 50000
#define DD 128
#define EE 500000
#define NWT (EE / 16)    // 31250 pair-tiles per side, exact

// ---------------- device scratch ----------------
static __device__ __nv_bfloat16 g_A1a[NN*DD];   // lrelu(x_a@Wp.T+bp)@W1p.T + b1
static __device__ __nv_bfloat16 g_C1a[NN*DD];   // lrelu(x_a@Wc.T+bc)@W1c.T
static __device__ __nv_bfloat16 g_A1b[NN*DD];
static __device__ __nv_bfloat16 g_C1b[NN*DD];
static __device__ __nv_bfloat16 g_xa16[NN*DD];  // bf16 copies of x (gather path)
static __device__ __nv_bfloat16 g_xb16[NN*DD];
static __device__ float g_msg_a[NN*DD];
static __device__ float g_msg_b[NN*DD];

__device__ __forceinline__ uint32_t smem_u32(const void* p) {
    uint32_t a;
    asm("{ .reg .u64 t; cvta.to.shared.u64 t, %1; cvt.u32.u64 %0, t; }" : "=r"(a) : "l"(p));
    return a;
}
__device__ __forceinline__ void ldsm_x4(uint32_t* r, uint32_t addr) {
    asm volatile("ldmatrix.sync.aligned.m8n8.x4.shared.b16 {%0,%1,%2,%3}, [%4];"
                 : "=r"(r[0]), "=r"(r[1]), "=r"(r[2]), "=r"(r[3]) : "r"(addr));
}
__device__ __forceinline__ void ldsm_x2(uint32_t* r, uint32_t addr) {
    asm volatile("ldmatrix.sync.aligned.m8n8.x2.shared.b16 {%0,%1}, [%2];"
                 : "=r"(r[0]), "=r"(r[1]) : "r"(addr));
}
__device__ __forceinline__ void mma_bf16(float* c, const uint32_t* a, const uint32_t* b) {
    asm volatile("mma.sync.aligned.m16n8k16.row.col.f32.bf16.bf16.f32 "
                 "{%0,%1,%2,%3}, {%4,%5,%6,%7}, {%8,%9}, {%0,%1,%2,%3};"
                 : "+f"(c[0]), "+f"(c[1]), "+f"(c[2]), "+f"(c[3])
                 : "r"(a[0]), "r"(a[1]), "r"(a[2]), "r"(a[3]), "r"(b[0]), "r"(b[1]));
}
__device__ __forceinline__ void mma_tf32(float* c, const uint32_t* a, const uint32_t* b) {
    asm volatile("mma.sync.aligned.m16n8k8.row.col.f32.tf32.tf32.f32 "
                 "{%0,%1,%2,%3}, {%4,%5,%6,%7}, {%8,%9}, {%0,%1,%2,%3};"
                 : "+f"(c[0]), "+f"(c[1]), "+f"(c[2]), "+f"(c[3])
                 : "r"(a[0]), "r"(a[1]), "r"(a[2]), "r"(a[3]), "r"(b[0]), "r"(b[1]));
}
__device__ __forceinline__ uint32_t f2tf32(float f) {
    uint32_t r;
    asm("cvt.rna.tf32.f32 %0, %1;" : "=r"(r) : "f"(f));
    return r;
}
__device__ __forceinline__ void red_add_v4(float* p, float a, float b, float c, float d) {
    asm volatile("red.global.add.v4.f32 [%0], {%1, %2, %3, %4};"
                 :: "l"(p), "f"(a), "f"(b), "f"(c), "f"(d) : "memory");
}
__device__ __forceinline__ __nv_bfloat162 u2bf2(uint32_t u) {
    return *reinterpret_cast<__nv_bfloat162*>(&u);
}
__device__ __forceinline__ uint32_t bf2u(__nv_bfloat162 h) {
    return *reinterpret_cast<uint32_t*>(&h);
}

// 16-row x 128-col x K=128 warp MMA over stride-272 bf16 smem tiles; accumulates.
__device__ __forceinline__ void mma_rows16(uint32_t a_addr0, uint32_t b_base, float acc[16][4]) {
    #pragma unroll
    for (int k = 0; k < 8; k++) {
        uint32_t afrag[4];
        ldsm_x4(afrag, a_addr0 + k * 32);
        uint32_t bb = b_base + k * 32;
        #pragma unroll
        for (int nt = 0; nt < 16; nt++) {
            uint32_t bfrag[2];
            ldsm_x2(bfrag, bb + nt * 2176);
            mma_bf16(acc[nt], afrag, bfrag);
        }
    }
}

// ---------------- node precompute: fused zero/cvt prologue + merged chains ----------------
#define NP_WT   0         // bf16 [128][272] -> 34816
#define NP_UT   34816     // bf16 [128][272] -> 69632
#define NP_XS   69632     // bf16 [256][272] -> 139264
#define NP_TS   139264    // bf16 [256][272] -> 208896
#define NP_BENC 208896    // 2 x 128 floats (bp, bc)
#define NP_B1   209920    // 128 floats
#define NP_TOTAL 210432

__global__ __launch_bounds__(512, 1) void node_pre_kernel(
    const float* __restrict__ x_a, const float* __restrict__ x_b,
    const float* __restrict__ Wp, const float* __restrict__ bp,
    const float* __restrict__ Wc, const float* __restrict__ bc,
    const float* __restrict__ W1, const float* __restrict__ b1)
{
    extern __shared__ char smc[];
    uint32_t smb = smem_u32(smc);
    float* benc = (float*)(smc + NP_BENC);
    float* b1sm = (float*)(smc + NP_B1);

    int sidex = blockIdx.y;
    const float* X = sidex ? x_b : x_a;
    __nv_bfloat16* OutA = sidex ? g_A1b : g_A1a;
    __nv_bfloat16* OutC = sidex ? g_C1b : g_C1a;

    int tid = threadIdx.x, lane = tid & 31, w = tid >> 5;
    int nbase = blockIdx.x * 256;

    // ---- fused: zero msg + make bf16 x copies (grid-stride over all 392 blocks) ----
    {
        int gbid = blockIdx.y * gridDim.x + blockIdx.x;
        int gstride = gridDim.x * 2 * 512;
        for (int i = gbid * 512 + tid; i < NN * DD / 4; i += gstride) {
            float4 z = make_float4(0.f, 0.f, 0.f, 0.f);
            reinterpret_cast<float4*>(g_msg_a)[i] = z;
            reinterpret_cast<float4*>(g_msg_b)[i] = z;
            float4 a = reinterpret_cast<const float4*>(x_a)[i];
            float4 b = reinterpret_cast<const float4*>(x_b)[i];
            uint2 pa, pb;
            pa.x = bf2u(__floats2bfloat162_rn(a.x, a.y));
            pa.y = bf2u(__floats2bfloat162_rn(a.z, a.w));
            pb.x = bf2u(__floats2bfloat162_rn(b.x, b.y));
            pb.y = bf2u(__floats2bfloat162_rn(b.z, b.w));
            reinterpret_cast<uint2*>(g_xa16)[i] = pa;
            reinterpret_cast<uint2*>(g_xb16)[i] = pb;
        }
    }

    for (int idx = tid; idx < 256 * 32; idx += 512) {
        int row = idx >> 5, cp = idx & 31;
        int n = nbase + row;
        float4 f = make_float4(0.f, 0.f, 0.f, 0.f);
        if (n < NN) f = *reinterpret_cast<const float4*>(X + (size_t)n * 128 + cp * 4);
        uint2 pk;
        pk.x = bf2u(__floats2bfloat162_rn(f.x, f.y));
        pk.y = bf2u(__floats2bfloat162_rn(f.z, f.w));
        *reinterpret_cast<uint2*>(smc + NP_XS + row * 272 + cp * 8) = pk;
    }
    if (tid < 128) {
        benc[tid]       = bp[tid];
        benc[128 + tid] = bc[tid];
        b1sm[tid]       = b1[tid];
    }

    uint32_t a_lane_off = (uint32_t)(lane & 15) * 272 + (((uint32_t)lane >> 4) << 4);
    uint32_t b_lane_off = (uint32_t)(lane & 7) * 272 + ((((uint32_t)lane >> 3) & 1) << 4);
    int r0 = 16 * w + (lane >> 2), r1 = r0 + 8;
    int cq = (lane & 3) * 2;
    int n0 = nbase + r0, n1 = nbase + r1;

    for (int cc = 0; cc < 2; cc++) {
        const float* W = cc ? Wc : Wp;
        int off = cc ? 128 : 0;
        __nv_bfloat16* Out = cc ? OutC : OutA;

        for (int idx = tid; idx < 128 * 64; idx += 512) {
            int i = idx >> 6, cp = idx & 63;
            float2 fw = *reinterpret_cast<const float2*>(W + i * 128 + cp * 2);
            float2 fu = *reinterpret_cast<const float2*>(W1 + i * 384 + off + cp * 2);
            *(uint32_t*)(smc + NP_WT + i * 272 + cp * 4) = bf2u(__floats2bfloat162_rn(fw.x, fw.y));
            *(uint32_t*)(smc + NP_UT + i * 272 + cp * 4) = bf2u(__floats2bfloat162_rn(fu.x, fu.y));
        }
        __syncthreads();

        float acc[16][4];
        #pragma unroll
        for (int nt = 0; nt < 16; nt++)
            #pragma unroll
            for (int q = 0; q < 4; q++) acc[nt][q] = 0.f;
        mma_rows16(smb + NP_XS + (uint32_t)(16 * w) * 272 + a_lane_off, smb + NP_WT + b_lane_off, acc);

        #pragma unroll
        for (int nt = 0; nt < 16; nt++) {
            int c = nt * 8 + cq;
            float2 bb = *reinterpret_cast<const float2*>(benc + cc * 128 + c);
            float v0 = acc[nt][0] + bb.x, v1 = acc[nt][1] + bb.y;
            float v2 = acc[nt][2] + bb.x, v3 = acc[nt][3] + bb.y;
            v0 = v0 > 0.f ? v0 : 0.01f * v0;
            v1 = v1 > 0.f ? v1 : 0.01f * v1;
            v2 = v2 > 0.f ? v2 : 0.01f * v2;
            v3 = v3 > 0.f ? v3 : 0.01f * v3;
            *(uint32_t*)(smc + NP_TS + r0 * 272 + c * 2) = bf2u(__floats2bfloat162_rn(v0, v1));
            *(uint32_t*)(smc + NP_TS + r1 * 272 + c * 2) = bf2u(__floats2bfloat162_rn(v2, v3));
        }
        __syncwarp();

        #pragma unroll
        for (int nt = 0; nt < 16; nt++)
            #pragma unroll
            for (int q = 0; q < 4; q++) acc[nt][q] = 0.f;
        mma_rows16(smb + NP_TS + (uint32_t)(16 * w) * 272 + a_lane_off, smb + NP_UT + b_lane_off, acc);

        #pragma unroll
        for (int nt = 0; nt < 16; nt++) {
            int c = nt * 8 + cq;
            float bx = (cc == 0) ? b1sm[c] : 0.f;
            float by = (cc == 0) ? b1sm[c + 1] : 0.f;
            uint32_t h0 = bf2u(__floats2bfloat162_rn(acc[nt][0] + bx, acc[nt][1] + by));
            uint32_t h1 = bf2u(__floats2bfloat162_rn(acc[nt][2] + bx, acc[nt][3] + by));
            if (n0 < NN) *(uint32_t*)(Out + (size_t)n0 * 128 + c) = h0;
            if (n1 < NN) *(uint32_t*)(Out + (size_t)n1 * 128 + c) = h1;
        }
        __syncthreads();
    }
}

// ---------------- edge kernel: merged sides by CTA range, warp-pair tiles ----------------
#define EP_W2   0          // 128 floats -> 512
#define EP_W1D  512        // bf16 [128][272] -> 35328
#define EP_DIFF 35328      // 4 pairs x 16x272 -> 52736
#define EP_PRES 52736      // 4 pairs x 16x272 -> 70144
#define EP_ZB   70144      // 4 pairs x 32 floats -> 70656
#define EP_TOTAL 70656

__global__ __launch_bounds__(256, 2) void edge_mma_kernel(
    const float* __restrict__ x_a, const float* __restrict__ x_b,
    const int* __restrict__ ei_ab, const int* __restrict__ ei_ba,
    const float* __restrict__ W1,
    const float* __restrict__ W2, const float* __restrict__ b2)
{
    extern __shared__ char smc[];
    uint32_t smb = smem_u32(smc);
    float* w2s  = (float*)(smc + EP_W2);
    float* zbuf = (float*)(smc + EP_ZB);

    int half = gridDim.x >> 1;
    int side = (blockIdx.x >= half) ? 1 : 0;
    int bx = blockIdx.x - side * half;
    const int* ei = side ? ei_ba : ei_ab;

    const float* src = side ? x_b : x_a;                     // fp32, scatter only
    const __nv_bfloat16* s16 = side ? g_xb16 : g_xa16;
    const __nv_bfloat16* d16 = side ? g_xa16 : g_xb16;
    const __nv_bfloat16* A1 = side ? g_A1b : g_A1a;
    const __nv_bfloat16* C1 = side ? g_C1a : g_C1b;
    float* msg              = side ? g_msg_a : g_msg_b;

    int tid = threadIdx.x, lane = tid & 31, w = tid >> 5;
    int pair = w >> 1, hf = w & 1;

    for (int idx = tid; idx < 128 * 64; idx += 256) {
        int i = idx >> 6, cp = idx & 63;
        float2 f = *reinterpret_cast<const float2*>(W1 + i * 384 + 256 + cp * 2);
        *(uint32_t*)(smc + EP_W1D + i * 272 + cp * 4) = bf2u(__floats2bfloat162_rn(f.x, f.y));
    }
    if (tid < 128) w2s[tid] = W2[tid];
    float b2s = __ldg(b2);
    __syncthreads();

    uint32_t tile_off = (uint32_t)pair * 4352;
    uint32_t a_addr0 = smb + EP_DIFF + tile_off + (uint32_t)(lane & 15) * 272 + (((uint32_t)lane >> 4) << 4);
    uint32_t b_base  = smb + EP_W1D + (uint32_t)(lane & 7) * 272 + ((((uint32_t)lane >> 3) & 1) << 4)
                     + (uint32_t)hf * (8 * 2176);
    int r0 = lane >> 2, r1 = r0 + 8;      // rows within the pair tile
    int cq = (lane & 3) * 2;
    int chf = hf * 64;
    int li16 = lane & 15;
    int isdst = lane >> 4;
    int zidx = pair * 32;

    const int pstride = half * 4;
    int pt = bx * 4 + pair;
    if (pt >= NWT) return;

    int vidx = __ldg(ei + isdst * EE + pt * 16 + li16);

    while (true) {
        // ---- register-staged gather: all 32 loads in flight before processing ----
        uint2 pu[8], cu[8], a1r[8], c1r[8];
        #pragma unroll
        for (int i = 0; i < 8; i++) {
            int ii = 8 * hf + i;
            int s = __shfl_sync(0xffffffffu, vidx, ii);
            int t = __shfl_sync(0xffffffffu, vidx, 16 + ii);
            pu[i]  = *reinterpret_cast<const uint2*>(s16 + (size_t)s * 128 + 4 * lane);
            cu[i]  = *reinterpret_cast<const uint2*>(d16 + (size_t)t * 128 + 4 * lane);
            a1r[i] = *reinterpret_cast<const uint2*>(A1  + (size_t)s * 128 + 4 * lane);
            c1r[i] = *reinterpret_cast<const uint2*>(C1  + (size_t)t * 128 + 4 * lane);
        }
        #pragma unroll
        for (int i = 0; i < 8; i++) {
            int ii = 8 * hf + i;
            uint2 dpk, ppk;
            dpk.x = bf2u(__habs2(__hsub2(u2bf2(pu[i].x), u2bf2(cu[i].x))));
            dpk.y = bf2u(__habs2(__hsub2(u2bf2(pu[i].y), u2bf2(cu[i].y))));
            ppk.x = bf2u(__hadd2(u2bf2(a1r[i].x), u2bf2(c1r[i].x)));
            ppk.y = bf2u(__hadd2(u2bf2(a1r[i].y), u2bf2(c1r[i].y)));
            *reinterpret_cast<uint2*>(smc + EP_DIFF + tile_off + ii * 272 + lane * 8) = dpk;
            *reinterpret_cast<uint2*>(smc + EP_PRES + tile_off + ii * 272 + lane * 8) = ppk;
        }
        asm volatile("bar.sync %0, 64;" :: "r"(pair + 1) : "memory");

        // ---- prefetch next pair-tile's indices ----
        int ptn = pt + pstride;
        int vnext = 0;
        if (ptn < NWT) vnext = __ldg(ei + isdst * EE + ptn * 16 + li16);

        // ---- mma: this warp's 8 n-tiles (64 cols) over the shared 16 rows ----
        float acc[8][4];
        #pragma unroll
        for (int nt = 0; nt < 8; nt++)
            #pragma unroll
            for (int q = 0; q < 4; q++) acc[nt][q] = 0.f;
        #pragma unroll
        for (int k = 0; k < 8; k++) {
            uint32_t afrag[4];
            ldsm_x4(afrag, a_addr0 + k * 32);
            uint32_t bb = b_base + k * 32;
            #pragma unroll
            for (int nt = 0; nt < 8; nt++) {
                uint32_t bfrag[2];
                ldsm_x2(bfrag, bb + nt * 2176);
                mma_bf16(acc[nt], afrag, bfrag);
            }
        }

        // ---- epilogue: partial z over this warp's 64 cols ----
        float z0 = 0.f, z1 = 0.f;
        #pragma unroll
        for (int nt = 0; nt < 8; nt++) {
            int c = chf + nt * 8 + cq;
            float2 p0 = __bfloat1622float2(*reinterpret_cast<const __nv_bfloat162*>(smc + EP_PRES + tile_off + r0 * 272 + c * 2));
            float2 p1 = __bfloat1622float2(*reinterpret_cast<const __nv_bfloat162*>(smc + EP_PRES + tile_off + r1 * 272 + c * 2));
            float2 w2v = *reinterpret_cast<const float2*>(w2s + c);
            z0 += fmaxf(p0.x + acc[nt][0], 0.f) * w2v.x + fmaxf(p0.y + acc[nt][1], 0.f) * w2v.y;
            z1 += fmaxf(p1.x + acc[nt][2], 0.f) * w2v.x + fmaxf(p1.y + acc[nt][3], 0.f) * w2v.y;
        }
        z0 += __shfl_xor_sync(0xffffffffu, z0, 1);
        z0 += __shfl_xor_sync(0xffffffffu, z0, 2);
        z1 += __shfl_xor_sync(0xffffffffu, z1, 1);
        z1 += __shfl_xor_sync(0xffffffffu, z1, 2);
        if ((lane & 3) == 0) {
            zbuf[zidx + hf * 16 + r0] = z0;
            zbuf[zidx + hf * 16 + r1] = z1;
        }
        asm volatile("bar.sync %0, 64;" :: "r"(pair + 1) : "memory");

        // ---- combine halves + sigmoid (lanes 0-15 own edge `lane`) ----
        float wg_l = 0.f;
        if (lane < 16) {
            float zz = zbuf[zidx + lane] + zbuf[zidx + 16 + lane] + b2s;
            wg_l = 1.f / (1.f + __expf(-zz));
        }

        // ---- register-staged scatter: all 8 src rows in flight, then reds ----
        float4 ps[8];
        #pragma unroll
        for (int i = 0; i < 8; i++) {
            int ii = 8 * hf + i;
            int s = __shfl_sync(0xffffffffu, vidx, ii);
            ps[i] = *reinterpret_cast<const float4*>(src + (size_t)s * 128 + 4 * lane);
        }
        #pragma unroll
        for (int i = 0; i < 8; i++) {
            int ii = 8 * hf + i;
            int t = __shfl_sync(0xffffffffu, vidx, 16 + ii);
            float wg = __shfl_sync(0xffffffffu, wg_l, ii);
            float* mr = msg + (size_t)t * 128 + 4 * lane;
            red_add_v4(mr, wg * ps[i].x, wg * ps[i].y, wg * ps[i].z, wg * ps[i].w);
        }

        if (ptn >= NWT) break;
        pt = ptn;
        vidx = vnext;
    }
}

// ---------------- final: single-pass tf32 mma ----------------
#define FT_A    0
#define FT_B    135168
#define FT_BS   202752
#define FT_TOTAL 203264

__global__ __launch_bounds__(512, 1) void final_kernel(
    const float* __restrict__ x_a, const float* __restrict__ x_b,
    const float* __restrict__ Wrel_ab, const float* __restrict__ brel_ab,
    const float* __restrict__ Wroot_ab, const float* __restrict__ broot_ab,
    const float* __restrict__ Wrel_ba, const float* __restrict__ brel_ba,
    const float* __restrict__ Wroot_ba, const float* __restrict__ broot_ba,
    float* __restrict__ out)
{
    extern __shared__ char smc[];
    float* bsf = (float*)(smc + FT_BS);

    int side = blockIdx.y;
    const float* x     = side ? x_b : x_a;
    const float* msg   = side ? g_msg_b : g_msg_a;
    const float* Wrel  = side ? Wrel_ab  : Wrel_ba;
    const float* brel  = side ? brel_ab  : brel_ba;
    const float* Wroot = side ? Wroot_ab : Wroot_ba;
    const float* broot = side ? broot_ab : broot_ba;
    float* o = out + (size_t)side * NN * DD;

    int tid = threadIdx.x, lane = tid & 31, w = tid >> 5;
    int nbase = blockIdx.x * 256;

    if (tid < 128) bsf[tid] = brel[tid] + broot[tid];

    uint32_t a_lane = (uint32_t)((lane >> 2) * 528 + (lane & 3) * 4);
    uint32_t b_lane = a_lane;

    float acc[16][4];
    #pragma unroll
    for (int nt = 0; nt < 16; nt++)
        #pragma unroll
        for (int q = 0; q < 4; q++) acc[nt][q] = 0.f;

    for (int term = 0; term < 2; term++) {
        const float* Asrc = term ? x : msg;
        const float* Bsrc = term ? Wroot : Wrel;
        if (term) __syncthreads();

        for (int idx = tid; idx < 128 * 64; idx += 512) {
            int i = idx >> 6, cp = idx & 63;
            float2 v = *reinterpret_cast<const float2*>(Bsrc + i * 128 + cp * 2);
            uint2 t;
            t.x = f2tf32(v.x);
            t.y = f2tf32(v.y);
            *reinterpret_cast<uint2*>(smc + FT_B + i * 528 + cp * 8) = t;
        }
        for (int idx = tid; idx < 256 * 32; idx += 512) {
            int row = idx >> 5, cp = idx & 31;
            int n = nbase + row;
            float4 v = make_float4(0.f, 0.f, 0.f, 0.f);
            if (n < NN) v = *reinterpret_cast<const float4*>(Asrc + (size_t)n * 128 + cp * 4);
            uint4 t;
            t.x = f2tf32(v.x);
            t.y = f2tf32(v.y);
            t.z = f2tf32(v.z);
            t.w = f2tf32(v.w);
            *reinterpret_cast<uint4*>(smc + FT_A + row * 528 + cp * 16) = t;
        }
        __syncthreads();

        const char* abase = smc + FT_A + (uint32_t)(16 * w) * 528 + a_lane;
        const char* bbase = smc + FT_B + b_lane;
        #pragma unroll
        for (int k = 0; k < 16; k++) {
            uint32_t af[4];
            const char* ak = abase + k * 32;
            af[0] = *(const uint32_t*)(ak);
            af[1] = *(const uint32_t*)(ak + 8 * 528);
            af[2] = *(const uint32_t*)(ak + 16);
            af[3] = *(const uint32_t*)(ak + 8 * 528 + 16);
            const char* bk = bbase + k * 32;
            #pragma unroll
            for (int nt = 0; nt < 16; nt++) {
                uint32_t bf[2];
                const char* bn = bk + nt * 8 * 528;
                bf[0] = *(const uint32_t*)(bn);
                bf[1] = *(const uint32_t*)(bn + 16);
                mma_tf32(acc[nt], af, bf);
            }
        }
    }

    int r0 = 16 * w + (lane >> 2), r1 = r0 + 8;
    int cq = (lane & 3) * 2;
    int n0 = nbase + r0, n1 = nbase + r1;
    #pragma unroll
    for (int nt = 0; nt < 16; nt++) {
        int c = nt * 8 + cq;
        float2 bb = *reinterpret_cast<const float2*>(bsf + c);
        if (n0 < NN) {
            float2 v = make_float2(acc[nt][0] + bb.x, acc[nt][1] + bb.y);
            *reinterpret_cast<float2*>(o + (size_t)n0 * 128 + c) = v;
        }
        if (n1 < NN) {
            float2 v = make_float2(acc[nt][2] + bb.x, acc[nt][3] + bb.y);
            *reinterpret_cast<float2*>(o + (size_t)n1 * 128 + c) = v;
        }
    }
}

// ---------------- host ----------------
extern "C" void kernel_launch(void* const* d_in, const int* in_sizes, int n_in,
                              void* d_out, int out_size)
{
    const float* x_a = (const float*)d_in[0];
    const float* x_b = (const float*)d_in[1];
    const float* Wp  = (const float*)d_in[2];
    const float* bp  = (const float*)d_in[3];
    const float* Wc  = (const float*)d_in[4];
    const float* bc  = (const float*)d_in[5];
    const float* W1  = (const float*)d_in[6];
    const float* b1  = (const float*)d_in[7];
    const float* W2  = (const float*)d_in[8];
    const float* b2  = (const float*)d_in[9];
    const float* Wrel_ab  = (const float*)d_in[10];
    const float* brel_ab  = (const float*)d_in[11];
    const float* Wroot_ab = (const float*)d_in[12];
    const float* broot_ab = (const float*)d_in[13];
    const float* Wrel_ba  = (const float*)d_in[14];
    const float* brel_ba  = (const float*)d_in[15];
    const float* Wroot_ba = (const float*)d_in[16];
    const float* broot_ba = (const float*)d_in[17];
    const int* ei_ab = (const int*)d_in[18];
    const int* ei_ba = (const int*)d_in[19];
    float* out = (float*)d_out;

    cudaFuncSetAttribute(node_pre_kernel, cudaFuncAttributeMaxDynamicSharedMemorySize, NP_TOTAL);
    cudaFuncSetAttribute(edge_mma_kernel, cudaFuncAttributeMaxDynamicSharedMemorySize, EP_TOTAL);
    cudaFuncSetAttribute(final_kernel,    cudaFuncAttributeMaxDynamicSharedMemorySize, FT_TOTAL);

    node_pre_kernel<<<dim3((NN + 255) / 256, 2), 512, NP_TOTAL>>>(x_a, x_b, Wp, bp, Wc, bc, W1, b1);
    edge_mma_kernel<<<592, 256, EP_TOTAL>>>(x_a, x_b, ei_ab, ei_ba, W1, W2, b2);
    final_kernel<<<dim3((NN + 255) / 256, 2), 512, FT_TOTAL>>>(
        x_a, x_b, Wrel_ab, brel_ab, Wroot_ab, broot_ab,
        Wrel_ba, brel_ba, Wroot_ba, broot_ba, out);
}

// round 16
// speedup vs baseline: 1.2545x; 1.0197x over previous
#include <cuda_runtime.h>
#include <cuda_bf16.h>
#include <math.h>
#include <stdint.h>

#define NN 50000
#define DD 128
#define EE 500000
#define NWT (EE / 16)    // 31250 pair-tiles per side, exact

// ---------------- device scratch ----------------
static __device__ __nv_bfloat16 g_A1a[NN*DD];   // lrelu(x_a@Wp.T+bp)@W1p.T + b1
static __device__ __nv_bfloat16 g_C1a[NN*DD];   // lrelu(x_a@Wc.T+bc)@W1c.T
static __device__ __nv_bfloat16 g_A1b[NN*DD];
static __device__ __nv_bfloat16 g_C1b[NN*DD];
static __device__ __nv_bfloat16 g_xa16[NN*DD];  // bf16 copies of x (gather path)
static __device__ __nv_bfloat16 g_xb16[NN*DD];
static __device__ float g_msg_a[NN*DD];
static __device__ float g_msg_b[NN*DD];

__device__ __forceinline__ uint32_t smem_u32(const void* p) {
    uint32_t a;
    asm("{ .reg .u64 t; cvta.to.shared.u64 t, %1; cvt.u32.u64 %0, t; }" : "=r"(a) : "l"(p));
    return a;
}
__device__ __forceinline__ void ldsm_x4(uint32_t* r, uint32_t addr) {
    asm volatile("ldmatrix.sync.aligned.m8n8.x4.shared.b16 {%0,%1,%2,%3}, [%4];"
                 : "=r"(r[0]), "=r"(r[1]), "=r"(r[2]), "=r"(r[3]) : "r"(addr));
}
__device__ __forceinline__ void ldsm_x2(uint32_t* r, uint32_t addr) {
    asm volatile("ldmatrix.sync.aligned.m8n8.x2.shared.b16 {%0,%1}, [%2];"
                 : "=r"(r[0]), "=r"(r[1]) : "r"(addr));
}
__device__ __forceinline__ void mma_bf16(float* c, const uint32_t* a, const uint32_t* b) {
    asm volatile("mma.sync.aligned.m16n8k16.row.col.f32.bf16.bf16.f32 "
                 "{%0,%1,%2,%3}, {%4,%5,%6,%7}, {%8,%9}, {%0,%1,%2,%3};"
                 : "+f"(c[0]), "+f"(c[1]), "+f"(c[2]), "+f"(c[3])
                 : "r"(a[0]), "r"(a[1]), "r"(a[2]), "r"(a[3]), "r"(b[0]), "r"(b[1]));
}
__device__ __forceinline__ void mma_tf32(float* c, const uint32_t* a, const uint32_t* b) {
    asm volatile("mma.sync.aligned.m16n8k8.row.col.f32.tf32.tf32.f32 "
                 "{%0,%1,%2,%3}, {%4,%5,%6,%7}, {%8,%9}, {%0,%1,%2,%3};"
                 : "+f"(c[0]), "+f"(c[1]), "+f"(c[2]), "+f"(c[3])
                 : "r"(a[0]), "r"(a[1]), "r"(a[2]), "r"(a[3]), "r"(b[0]), "r"(b[1]));
}
__device__ __forceinline__ uint32_t f2tf32(float f) {
    uint32_t r;
    asm("cvt.rna.tf32.f32 %0, %1;" : "=r"(r) : "f"(f));
    return r;
}
__device__ __forceinline__ void red_add_v4(float* p, float a, float b, float c, float d) {
    asm volatile("red.global.add.v4.f32 [%0], {%1, %2, %3, %4};"
                 :: "l"(p), "f"(a), "f"(b), "f"(c), "f"(d) : "memory");
}
__device__ __forceinline__ __nv_bfloat162 u2bf2(uint32_t u) {
    return *reinterpret_cast<__nv_bfloat162*>(&u);
}
__device__ __forceinline__ uint32_t bf2u(__nv_bfloat162 h) {
    return *reinterpret_cast<uint32_t*>(&h);
}

// 16-row x 128-col x K=128 warp MMA over stride-272 bf16 smem tiles; accumulates.
__device__ __forceinline__ void mma_rows16(uint32_t a_addr0, uint32_t b_base, float acc[16][4]) {
    #pragma unroll
    for (int k = 0; k < 8; k++) {
        uint32_t afrag[4];
        ldsm_x4(afrag, a_addr0 + k * 32);
        uint32_t bb = b_base + k * 32;
        #pragma unroll
        for (int nt = 0; nt < 16; nt++) {
            uint32_t bfrag[2];
            ldsm_x2(bfrag, bb + nt * 2176);
            mma_bf16(acc[nt], afrag, bfrag);
        }
    }
}

// ---------------- node precompute: msg-zero prologue, x16 from tile, merged chains ----------------
#define NP_WT   0         // bf16 [128][272] -> 34816
#define NP_UT   34816     // bf16 [128][272] -> 69632
#define NP_XS   69632     // bf16 [256][272] -> 139264
#define NP_TS   139264    // bf16 [256][272] -> 208896
#define NP_BENC 208896    // 2 x 128 floats (bp, bc)
#define NP_B1   209920    // 128 floats
#define NP_TOTAL 210432

__global__ __launch_bounds__(512, 1) void node_pre_kernel(
    const float* __restrict__ x_a, const float* __restrict__ x_b,
    const float* __restrict__ Wp, const float* __restrict__ bp,
    const float* __restrict__ Wc, const float* __restrict__ bc,
    const float* __restrict__ W1, const float* __restrict__ b1)
{
    extern __shared__ char smc[];
    uint32_t smb = smem_u32(smc);
    float* benc = (float*)(smc + NP_BENC);
    float* b1sm = (float*)(smc + NP_B1);

    int sidex = blockIdx.y;
    const float* X = sidex ? x_b : x_a;
    __nv_bfloat16* OutA = sidex ? g_A1b : g_A1a;
    __nv_bfloat16* OutC = sidex ? g_C1b : g_C1a;
    __nv_bfloat16* X16  = sidex ? g_xb16 : g_xa16;

    int tid = threadIdx.x, lane = tid & 31, w = tid >> 5;
    int nbase = blockIdx.x * 256;

    // ---- prologue: zero msg only (grid-stride over all blocks) ----
    {
        int gbid = blockIdx.y * gridDim.x + blockIdx.x;
        int gstride = gridDim.x * 2 * 512;
        float4 z = make_float4(0.f, 0.f, 0.f, 0.f);
        for (int i = gbid * 512 + tid; i < NN * DD / 4; i += gstride) {
            reinterpret_cast<float4*>(g_msg_a)[i] = z;
            reinterpret_cast<float4*>(g_msg_b)[i] = z;
        }
    }

    // ---- x tile -> bf16 XS; also persist to global x16 (coalesced) ----
    for (int idx = tid; idx < 256 * 32; idx += 512) {
        int row = idx >> 5, cp = idx & 31;
        int n = nbase + row;
        float4 f = make_float4(0.f, 0.f, 0.f, 0.f);
        if (n < NN) f = *reinterpret_cast<const float4*>(X + (size_t)n * 128 + cp * 4);
        uint2 pk;
        pk.x = bf2u(__floats2bfloat162_rn(f.x, f.y));
        pk.y = bf2u(__floats2bfloat162_rn(f.z, f.w));
        *reinterpret_cast<uint2*>(smc + NP_XS + row * 272 + cp * 8) = pk;
        if (n < NN) *reinterpret_cast<uint2*>(X16 + (size_t)n * 128 + cp * 4) = pk;
    }
    if (tid < 128) {
        benc[tid]       = bp[tid];
        benc[128 + tid] = bc[tid];
        b1sm[tid]       = b1[tid];
    }

    uint32_t a_lane_off = (uint32_t)(lane & 15) * 272 + (((uint32_t)lane >> 4) << 4);
    uint32_t b_lane_off = (uint32_t)(lane & 7) * 272 + ((((uint32_t)lane >> 3) & 1) << 4);
    int r0 = 16 * w + (lane >> 2), r1 = r0 + 8;
    int cq = (lane & 3) * 2;
    int n0 = nbase + r0, n1 = nbase + r1;

    for (int cc = 0; cc < 2; cc++) {
        const float* W = cc ? Wc : Wp;
        int off = cc ? 128 : 0;
        __nv_bfloat16* Out = cc ? OutC : OutA;

        for (int idx = tid; idx < 128 * 64; idx += 512) {
            int i = idx >> 6, cp = idx & 63;
            float2 fw = *reinterpret_cast<const float2*>(W + i * 128 + cp * 2);
            float2 fu = *reinterpret_cast<const float2*>(W1 + i * 384 + off + cp * 2);
            *(uint32_t*)(smc + NP_WT + i * 272 + cp * 4) = bf2u(__floats2bfloat162_rn(fw.x, fw.y));
            *(uint32_t*)(smc + NP_UT + i * 272 + cp * 4) = bf2u(__floats2bfloat162_rn(fu.x, fu.y));
        }
        __syncthreads();

        float acc[16][4];
        #pragma unroll
        for (int nt = 0; nt < 16; nt++)
            #pragma unroll
            for (int q = 0; q < 4; q++) acc[nt][q] = 0.f;
        mma_rows16(smb + NP_XS + (uint32_t)(16 * w) * 272 + a_lane_off, smb + NP_WT + b_lane_off, acc);

        #pragma unroll
        for (int nt = 0; nt < 16; nt++) {
            int c = nt * 8 + cq;
            float2 bb = *reinterpret_cast<const float2*>(benc + cc * 128 + c);
            float v0 = acc[nt][0] + bb.x, v1 = acc[nt][1] + bb.y;
            float v2 = acc[nt][2] + bb.x, v3 = acc[nt][3] + bb.y;
            v0 = v0 > 0.f ? v0 : 0.01f * v0;
            v1 = v1 > 0.f ? v1 : 0.01f * v1;
            v2 = v2 > 0.f ? v2 : 0.01f * v2;
            v3 = v3 > 0.f ? v3 : 0.01f * v3;
            *(uint32_t*)(smc + NP_TS + r0 * 272 + c * 2) = bf2u(__floats2bfloat162_rn(v0, v1));
            *(uint32_t*)(smc + NP_TS + r1 * 272 + c * 2) = bf2u(__floats2bfloat162_rn(v2, v3));
        }
        __syncwarp();

        #pragma unroll
        for (int nt = 0; nt < 16; nt++)
            #pragma unroll
            for (int q = 0; q < 4; q++) acc[nt][q] = 0.f;
        mma_rows16(smb + NP_TS + (uint32_t)(16 * w) * 272 + a_lane_off, smb + NP_UT + b_lane_off, acc);

        #pragma unroll
        for (int nt = 0; nt < 16; nt++) {
            int c = nt * 8 + cq;
            float bx = (cc == 0) ? b1sm[c] : 0.f;
            float by = (cc == 0) ? b1sm[c + 1] : 0.f;
            uint32_t h0 = bf2u(__floats2bfloat162_rn(acc[nt][0] + bx, acc[nt][1] + by));
            uint32_t h1 = bf2u(__floats2bfloat162_rn(acc[nt][2] + bx, acc[nt][3] + by));
            if (n0 < NN) *(uint32_t*)(Out + (size_t)n0 * 128 + c) = h0;
            if (n1 < NN) *(uint32_t*)(Out + (size_t)n1 * 128 + c) = h1;
        }
        __syncthreads();
    }
}

// ---------------- edge kernel: merged sides, pipelined gather ----------------
#define EP_W2   0          // 128 floats -> 512
#define EP_W1D  512        // bf16 [128][272] -> 35328
#define EP_DIFF 35328      // 4 pairs x 16x272 -> 52736
#define EP_PRES 52736      // 4 pairs x 16x272 -> 70144
#define EP_ZB   70144      // 4 pairs x 32 floats -> 70656
#define EP_TOTAL 70656

__global__ __launch_bounds__(256, 2) void edge_mma_kernel(
    const float* __restrict__ x_a, const float* __restrict__ x_b,
    const int* __restrict__ ei_ab, const int* __restrict__ ei_ba,
    const float* __restrict__ W1,
    const float* __restrict__ W2, const float* __restrict__ b2)
{
    extern __shared__ char smc[];
    uint32_t smb = smem_u32(smc);
    float* w2s  = (float*)(smc + EP_W2);
    float* zbuf = (float*)(smc + EP_ZB);

    int half = gridDim.x >> 1;
    int side = (blockIdx.x >= half) ? 1 : 0;
    int bx = blockIdx.x - side * half;
    const int* ei = side ? ei_ba : ei_ab;

    const float* src = side ? x_b : x_a;                     // fp32, scatter only
    const __nv_bfloat16* s16 = side ? g_xb16 : g_xa16;
    const __nv_bfloat16* d16 = side ? g_xa16 : g_xb16;
    const __nv_bfloat16* A1 = side ? g_A1b : g_A1a;
    const __nv_bfloat16* C1 = side ? g_C1a : g_C1b;
    float* msg              = side ? g_msg_a : g_msg_b;

    int tid = threadIdx.x, lane = tid & 31, w = tid >> 5;
    int pair = w >> 1, hf = w & 1;

    for (int idx = tid; idx < 128 * 64; idx += 256) {
        int i = idx >> 6, cp = idx & 63;
        float2 f = *reinterpret_cast<const float2*>(W1 + i * 384 + 256 + cp * 2);
        *(uint32_t*)(smc + EP_W1D + i * 272 + cp * 4) = bf2u(__floats2bfloat162_rn(f.x, f.y));
    }
    if (tid < 128) w2s[tid] = W2[tid];
    float b2s = __ldg(b2);
    __syncthreads();

    uint32_t tile_off = (uint32_t)pair * 4352;
    uint32_t a_addr0 = smb + EP_DIFF + tile_off + (uint32_t)(lane & 15) * 272 + (((uint32_t)lane >> 4) << 4);
    uint32_t b_base  = smb + EP_W1D + (uint32_t)(lane & 7) * 272 + ((((uint32_t)lane >> 3) & 1) << 4)
                     + (uint32_t)hf * (8 * 2176);
    int r0 = lane >> 2, r1 = r0 + 8;      // rows within the pair tile
    int cq = (lane & 3) * 2;
    int chf = hf * 64;
    int li16 = lane & 15;
    int isdst = lane >> 4;
    int zidx = pair * 32;

    const int pstride = half * 4;
    int pt = bx * 4 + pair;
    if (pt >= NWT) return;

    int vidx = __ldg(ei + isdst * EE + pt * 16 + li16);

    // prime the pipeline: stage tile-pt gather into registers
    uint2 pu[8], cu[8], a1r[8], c1r[8];
    #pragma unroll
    for (int i = 0; i < 8; i++) {
        int ii = 8 * hf + i;
        int s = __shfl_sync(0xffffffffu, vidx, ii);
        int t = __shfl_sync(0xffffffffu, vidx, 16 + ii);
        pu[i]  = *reinterpret_cast<const uint2*>(s16 + (size_t)s * 128 + 4 * lane);
        cu[i]  = *reinterpret_cast<const uint2*>(d16 + (size_t)t * 128 + 4 * lane);
        a1r[i] = *reinterpret_cast<const uint2*>(A1  + (size_t)s * 128 + 4 * lane);
        c1r[i] = *reinterpret_cast<const uint2*>(C1  + (size_t)t * 128 + 4 * lane);
    }

    while (true) {
        // ---- write staged gather to smem ----
        #pragma unroll
        for (int i = 0; i < 8; i++) {
            int ii = 8 * hf + i;
            uint2 dpk, ppk;
            dpk.x = bf2u(__habs2(__hsub2(u2bf2(pu[i].x), u2bf2(cu[i].x))));
            dpk.y = bf2u(__habs2(__hsub2(u2bf2(pu[i].y), u2bf2(cu[i].y))));
            ppk.x = bf2u(__hadd2(u2bf2(a1r[i].x), u2bf2(c1r[i].x)));
            ppk.y = bf2u(__hadd2(u2bf2(a1r[i].y), u2bf2(c1r[i].y)));
            *reinterpret_cast<uint2*>(smc + EP_DIFF + tile_off + ii * 272 + lane * 8) = dpk;
            *reinterpret_cast<uint2*>(smc + EP_PRES + tile_off + ii * 272 + lane * 8) = ppk;
        }
        asm volatile("bar.sync %0, 64;" :: "r"(pair + 1) : "memory");

        // ---- prefetch next tile's indices ----
        int ptn = pt + pstride;
        int more = ptn < NWT;
        int vnext = 0;
        if (more) vnext = __ldg(ei + isdst * EE + ptn * 16 + li16);

        float acc[8][4];
        #pragma unroll
        for (int nt = 0; nt < 8; nt++)
            #pragma unroll
            for (int q = 0; q < 4; q++) acc[nt][q] = 0.f;

        // ---- mma first half: k = 0..3 (hides index load) ----
        #pragma unroll
        for (int k = 0; k < 4; k++) {
            uint32_t afrag[4];
            ldsm_x4(afrag, a_addr0 + k * 32);
            uint32_t bb = b_base + k * 32;
            #pragma unroll
            for (int nt = 0; nt < 8; nt++) {
                uint32_t bfrag[2];
                ldsm_x2(bfrag, bb + nt * 2176);
                mma_bf16(acc[nt], afrag, bfrag);
            }
        }

        // ---- stage NEXT tile's gather (latency hides under remaining work) ----
        if (more) {
            #pragma unroll
            for (int i = 0; i < 8; i++) {
                int ii = 8 * hf + i;
                int s = __shfl_sync(0xffffffffu, vnext, ii);
                int t = __shfl_sync(0xffffffffu, vnext, 16 + ii);
                pu[i]  = *reinterpret_cast<const uint2*>(s16 + (size_t)s * 128 + 4 * lane);
                cu[i]  = *reinterpret_cast<const uint2*>(d16 + (size_t)t * 128 + 4 * lane);
                a1r[i] = *reinterpret_cast<const uint2*>(A1  + (size_t)s * 128 + 4 * lane);
                c1r[i] = *reinterpret_cast<const uint2*>(C1  + (size_t)t * 128 + 4 * lane);
            }
        }

        // ---- mma second half: k = 4..7 ----
        #pragma unroll
        for (int k = 4; k < 8; k++) {
            uint32_t afrag[4];
            ldsm_x4(afrag, a_addr0 + k * 32);
            uint32_t bb = b_base + k * 32;
            #pragma unroll
            for (int nt = 0; nt < 8; nt++) {
                uint32_t bfrag[2];
                ldsm_x2(bfrag, bb + nt * 2176);
                mma_bf16(acc[nt], afrag, bfrag);
            }
        }

        // ---- epilogue: partial z over this warp's 64 cols ----
        float z0 = 0.f, z1 = 0.f;
        #pragma unroll
        for (int nt = 0; nt < 8; nt++) {
            int c = chf + nt * 8 + cq;
            float2 p0 = __bfloat1622float2(*reinterpret_cast<const __nv_bfloat162*>(smc + EP_PRES + tile_off + r0 * 272 + c * 2));
            float2 p1 = __bfloat1622float2(*reinterpret_cast<const __nv_bfloat162*>(smc + EP_PRES + tile_off + r1 * 272 + c * 2));
            float2 w2v = *reinterpret_cast<const float2*>(w2s + c);
            z0 += fmaxf(p0.x + acc[nt][0], 0.f) * w2v.x + fmaxf(p0.y + acc[nt][1], 0.f) * w2v.y;
            z1 += fmaxf(p1.x + acc[nt][2], 0.f) * w2v.x + fmaxf(p1.y + acc[nt][3], 0.f) * w2v.y;
        }
        z0 += __shfl_xor_sync(0xffffffffu, z0, 1);
        z0 += __shfl_xor_sync(0xffffffffu, z0, 2);
        z1 += __shfl_xor_sync(0xffffffffu, z1, 1);
        z1 += __shfl_xor_sync(0xffffffffu, z1, 2);
        if ((lane & 3) == 0) {
            zbuf[zidx + hf * 16 + r0] = z0;
            zbuf[zidx + hf * 16 + r1] = z1;
        }
        asm volatile("bar.sync %0, 64;" :: "r"(pair + 1) : "memory");

        // ---- combine halves + sigmoid (lanes 0-15 own edge `lane`) ----
        float wg_l = 0.f;
        if (lane < 16) {
            float zz = zbuf[zidx + lane] + zbuf[zidx + 16 + lane] + b2s;
            wg_l = 1.f / (1.f + __expf(-zz));
        }

        // ---- register-staged scatter ----
        float4 ps[8];
        #pragma unroll
        for (int i = 0; i < 8; i++) {
            int ii = 8 * hf + i;
            int s = __shfl_sync(0xffffffffu, vidx, ii);
            ps[i] = *reinterpret_cast<const float4*>(src + (size_t)s * 128 + 4 * lane);
        }
        #pragma unroll
        for (int i = 0; i < 8; i++) {
            int ii = 8 * hf + i;
            int t = __shfl_sync(0xffffffffu, vidx, 16 + ii);
            float wg = __shfl_sync(0xffffffffu, wg_l, ii);
            float* mr = msg + (size_t)t * 128 + 4 * lane;
            red_add_v4(mr, wg * ps[i].x, wg * ps[i].y, wg * ps[i].z, wg * ps[i].w);
        }

        if (!more) break;
        pt = ptn;
        vidx = vnext;
    }
}

// ---------------- final: single-pass tf32 mma ----------------
#define FT_A    0
#define FT_B    135168
#define FT_BS   202752
#define FT_TOTAL 203264

__global__ __launch_bounds__(512, 1) void final_kernel(
    const float* __restrict__ x_a, const float* __restrict__ x_b,
    const float* __restrict__ Wrel_ab, const float* __restrict__ brel_ab,
    const float* __restrict__ Wroot_ab, const float* __restrict__ broot_ab,
    const float* __restrict__ Wrel_ba, const float* __restrict__ brel_ba,
    const float* __restrict__ Wroot_ba, const float* __restrict__ broot_ba,
    float* __restrict__ out)
{
    extern __shared__ char smc[];
    float* bsf = (float*)(smc + FT_BS);

    int side = blockIdx.y;
    const float* x     = side ? x_b : x_a;
    const float* msg   = side ? g_msg_b : g_msg_a;
    const float* Wrel  = side ? Wrel_ab  : Wrel_ba;
    const float* brel  = side ? brel_ab  : brel_ba;
    const float* Wroot = side ? Wroot_ab : Wroot_ba;
    const float* broot = side ? broot_ab : broot_ba;
    float* o = out + (size_t)side * NN * DD;

    int tid = threadIdx.x, lane = tid & 31, w = tid >> 5;
    int nbase = blockIdx.x * 256;

    if (tid < 128) bsf[tid] = brel[tid] + broot[tid];

    uint32_t a_lane = (uint32_t)((lane >> 2) * 528 + (lane & 3) * 4);
    uint32_t b_lane = a_lane;

    float acc[16][4];
    #pragma unroll
    for (int nt = 0; nt < 16; nt++)
        #pragma unroll
        for (int q = 0; q < 4; q++) acc[nt][q] = 0.f;

    for (int term = 0; term < 2; term++) {
        const float* Asrc = term ? x : msg;
        const float* Bsrc = term ? Wroot : Wrel;
        if (term) __syncthreads();

        for (int idx = tid; idx < 128 * 64; idx += 512) {
            int i = idx >> 6, cp = idx & 63;
            float2 v = *reinterpret_cast<const float2*>(Bsrc + i * 128 + cp * 2);
            uint2 t;
            t.x = f2tf32(v.x);
            t.y = f2tf32(v.y);
            *reinterpret_cast<uint2*>(smc + FT_B + i * 528 + cp * 8) = t;
        }
        for (int idx = tid; idx < 256 * 32; idx += 512) {
            int row = idx >> 5, cp = idx & 31;
            int n = nbase + row;
            float4 v = make_float4(0.f, 0.f, 0.f, 0.f);
            if (n < NN) v = *reinterpret_cast<const float4*>(Asrc + (size_t)n * 128 + cp * 4);
            uint4 t;
            t.x = f2tf32(v.x);
            t.y = f2tf32(v.y);
            t.z = f2tf32(v.z);
            t.w = f2tf32(v.w);
            *reinterpret_cast<uint4*>(smc + FT_A + row * 528 + cp * 16) = t;
        }
        __syncthreads();

        const char* abase = smc + FT_A + (uint32_t)(16 * w) * 528 + a_lane;
        const char* bbase = smc + FT_B + b_lane;
        #pragma unroll
        for (int k = 0; k < 16; k++) {
            uint32_t af[4];
            const char* ak = abase + k * 32;
            af[0] = *(const uint32_t*)(ak);
            af[1] = *(const uint32_t*)(ak + 8 * 528);
            af[2] = *(const uint32_t*)(ak + 16);
            af[3] = *(const uint32_t*)(ak + 8 * 528 + 16);
            const char* bk = bbase + k * 32;
            #pragma unroll
            for (int nt = 0; nt < 16; nt++) {
                uint32_t bf[2];
                const char* bn = bk + nt * 8 * 528;
                bf[0] = *(const uint32_t*)(bn);
                bf[1] = *(const uint32_t*)(bn + 16);
                mma_tf32(acc[nt], af, bf);
            }
        }
    }

    int r0 = 16 * w + (lane >> 2), r1 = r0 + 8;
    int cq = (lane & 3) * 2;
    int n0 = nbase + r0, n1 = nbase + r1;
    #pragma unroll
    for (int nt = 0; nt < 16; nt++) {
        int c = nt * 8 + cq;
        float2 bb = *reinterpret_cast<const float2*>(bsf + c);
        if (n0 < NN) {
            float2 v = make_float2(acc[nt][0] + bb.x, acc[nt][1] + bb.y);
            *reinterpret_cast<float2*>(o + (size_t)n0 * 128 + c) = v;
        }
        if (n1 < NN) {
            float2 v = make_float2(acc[nt][2] + bb.x, acc[nt][3] + bb.y);
            *reinterpret_cast<float2*>(o + (size_t)n1 * 128 + c) = v;
        }
    }
}

// ---------------- host ----------------
extern "C" void kernel_launch(void* const* d_in, const int* in_sizes, int n_in,
                              void* d_out, int out_size)
{
    const float* x_a = (const float*)d_in[0];
    const float* x_b = (const float*)d_in[1];
    const float* Wp  = (const float*)d_in[2];
    const float* bp  = (const float*)d_in[3];
    const float* Wc  = (const float*)d_in[4];
    const float* bc  = (const float*)d_in[5];
    const float* W1  = (const float*)d_in[6];
    const float* b1  = (const float*)d_in[7];
    const float* W2  = (const float*)d_in[8];
    const float* b2  = (const float*)d_in[9];
    const float* Wrel_ab  = (const float*)d_in[10];
    const float* brel_ab  = (const float*)d_in[11];
    const float* Wroot_ab = (const float*)d_in[12];
    const float* broot_ab = (const float*)d_in[13];
    const float* Wrel_ba  = (const float*)d_in[14];
    const float* brel_ba  = (const float*)d_in[15];
    const float* Wroot_ba = (const float*)d_in[16];
    const float* broot_ba = (const float*)d_in[17];
    const int* ei_ab = (const int*)d_in[18];
    const int* ei_ba = (const int*)d_in[19];
    float* out = (float*)d_out;

    cudaFuncSetAttribute(node_pre_kernel, cudaFuncAttributeMaxDynamicSharedMemorySize, NP_TOTAL);
    cudaFuncSetAttribute(edge_mma_kernel, cudaFuncAttributeMaxDynamicSharedMemorySize, EP_TOTAL);
    cudaFuncSetAttribute(final_kernel,    cudaFuncAttributeMaxDynamicSharedMemorySize, FT_TOTAL);

    node_pre_kernel<<<dim3((NN + 255) / 256, 2), 512, NP_TOTAL>>>(x_a, x_b, Wp, bp, Wc, bc, W1, b1);
    edge_mma_kernel<<<592, 256, EP_TOTAL>>>(x_a, x_b, ei_ab, ei_ba, W1, W2, b2);
    final_kernel<<<dim3((NN + 255) / 256, 2), 512, FT_TOTAL>>>(
        x_a, x_b, Wrel_ab, brel_ab, Wroot_ab, broot_ab,
        Wrel_ba, brel_ba, Wroot_ba, broot_ba, out);
}